// round 1
// baseline (speedup 1.0000x reference)
#include <cuda_runtime.h>
#include <math.h>

namespace {

constexpr int NTOK  = 4801;
constexpr int D     = 512;
constexpr int QKVW  = 1536;
constexpr int FRAMES= 4;
constexpr int NSP   = 1200;   // n (tokens per "frame" group)
constexpr int HALFN = 600;    // m
constexpr int NKEY  = 601;    // cls + half
constexpr int NHEAD = 8;
constexpr int DH    = 64;
constexpr float ASCALE = 0.125f;  // 1/sqrt(64)
constexpr int FF1   = 4096;
constexpr int FF2   = 2048;
constexpr int NPATCH= 4800;
constexpr int PD    = 768;
constexpr int NGRP  = 64;     // heads * frames * 2 halves

__device__ float g_x   [NTOK * D];
__device__ float g_xn  [NTOK * D];
__device__ float g_attn[NTOK * D];
__device__ float g_qkv [NTOK * QKVW];
__device__ float g_tok [NPATCH * PD];
__device__ float g_h   [NTOK * FF1];
__device__ float g_act [NTOK * FF2];
__device__ float g_S   [(size_t)NGRP * HALFN * NKEY];

// ---------------------------------------------------------------- SGEMM
// C[M,N] = A[M,K] @ B[K,N] (+bias[N]) (+resid[M,N])
// 128x64 tile, BK=16, 256 threads, 8x4 per-thread
__global__ void sgemm_kernel(const float* __restrict__ A, const float* __restrict__ B,
                             const float* __restrict__ bias, const float* __restrict__ resid,
                             float* __restrict__ C, int M, int N, int K)
{
    __shared__ float As[16][128];
    __shared__ float Bs[16][64];
    const int tid = threadIdx.x;
    const int tx = tid & 15, ty = tid >> 4;
    const int row0 = blockIdx.y * 128;
    const int col0 = blockIdx.x * 64;

    float acc[8][4];
#pragma unroll
    for (int a = 0; a < 8; a++)
#pragma unroll
        for (int b = 0; b < 4; b++) acc[a][b] = 0.f;

    for (int k0 = 0; k0 < K; k0 += 16) {
#pragma unroll
        for (int u = 0; u < 8; u++) {
            int idx = tid + u * 256;
            int r = idx >> 4, c = idx & 15;
            int gr = row0 + r;
            As[c][r] = (gr < M) ? A[(size_t)gr * K + k0 + c] : 0.f;
        }
#pragma unroll
        for (int u = 0; u < 4; u++) {
            int idx = tid + u * 256;
            int kk = idx >> 6, nn = idx & 63;
            int gc = col0 + nn;
            Bs[kk][nn] = (gc < N) ? B[(size_t)(k0 + kk) * N + gc] : 0.f;
        }
        __syncthreads();
#pragma unroll
        for (int k = 0; k < 16; k++) {
            float4 a0 = *reinterpret_cast<const float4*>(&As[k][ty * 8]);
            float4 a1 = *reinterpret_cast<const float4*>(&As[k][ty * 8 + 4]);
            float4 b0 = *reinterpret_cast<const float4*>(&Bs[k][tx * 4]);
            float ra[8] = {a0.x, a0.y, a0.z, a0.w, a1.x, a1.y, a1.z, a1.w};
            float rb[4] = {b0.x, b0.y, b0.z, b0.w};
#pragma unroll
            for (int a = 0; a < 8; a++)
#pragma unroll
                for (int b = 0; b < 4; b++) acc[a][b] += ra[a] * rb[b];
        }
        __syncthreads();
    }

#pragma unroll
    for (int a = 0; a < 8; a++) {
        int gr = row0 + ty * 8 + a;
        if (gr >= M) continue;
#pragma unroll
        for (int b = 0; b < 4; b++) {
            int gc = col0 + tx * 4 + b;
            if (gc >= N) continue;
            float v = acc[a][b];
            if (bias)  v += bias[gc];
            if (resid) v += resid[(size_t)gr * N + gc];
            C[(size_t)gr * N + gc] = v;
        }
    }
}

// ---------------------------------------------------------------- patchify
// tok[t, pd]; t<2400: left half (cols 0..319), else right half.
__global__ void patchify_kernel(const float* __restrict__ video, float* __restrict__ tok)
{
    int idx = blockIdx.x * blockDim.x + threadIdx.x;
    if (idx >= NPATCH * PD) return;
    int t = idx / PD, pd = idx % PD;
    int side = t / 2400;
    int r = t % 2400;
    int f = r / 600;
    int rr = r % 600;
    int ph = rr / 20;          // patch row (0..29)
    int pw = rr % 20;          // patch col within half (0..19)
    int p1 = pd / 48;
    int rem = pd % 48;
    int p2 = rem / 3;
    int c  = rem % 3;
    int row = ph * 16 + p1;
    int col = side * 320 + pw * 16 + p2;
    tok[idx] = video[(((size_t)f * 3 + c) * 480 + row) * 640 + col];
}

// ---------------------------------------------------------------- pos + cls
__global__ void addpos_kernel(float* __restrict__ x, const float* __restrict__ cls,
                              const float* __restrict__ pos)
{
    int idx = blockIdx.x * blockDim.x + threadIdx.x;
    if (idx >= NTOK * D) return;
    if (idx < D) x[idx] = cls[idx] + pos[idx];
    else         x[idx] += pos[idx];
}

// ---------------------------------------------------------------- LayerNorm
__global__ void layernorm_kernel(const float* __restrict__ x, const float* __restrict__ g,
                                 const float* __restrict__ b, float* __restrict__ out, int M)
{
    int row = blockIdx.x;
    if (row >= M) return;
    int tid = threadIdx.x;  // 256
    const float* xr = x + (size_t)row * D;
    float x0 = xr[tid], x1 = xr[tid + 256];
    __shared__ float red[8];

    float s = x0 + x1;
#pragma unroll
    for (int o = 16; o; o >>= 1) s += __shfl_xor_sync(0xffffffffu, s, o);
    if ((tid & 31) == 0) red[tid >> 5] = s;
    __syncthreads();
    if (tid == 0) { float t = 0; for (int i = 0; i < 8; i++) t += red[i]; red[0] = t; }
    __syncthreads();
    float mu = red[0] * (1.f / 512.f);
    __syncthreads();

    float d0 = x0 - mu, d1 = x1 - mu;
    float v = d0 * d0 + d1 * d1;
#pragma unroll
    for (int o = 16; o; o >>= 1) v += __shfl_xor_sync(0xffffffffu, v, o);
    if ((tid & 31) == 0) red[tid >> 5] = v;
    __syncthreads();
    if (tid == 0) { float t = 0; for (int i = 0; i < 8; i++) t += red[i]; red[0] = t; }
    __syncthreads();
    float rstd = rsqrtf(red[0] * (1.f / 512.f) + 1e-5f);

    out[(size_t)row * D + tid]       = d0 * rstd * g[tid] + b[tid];
    out[(size_t)row * D + tid + 256] = d1 * rstd * g[tid + 256] + b[tid + 256];
}

// ---------------------------------------------------------------- cls attention
// One block per head; cls query attends over all 4801 keys.
__global__ void cls_attn_kernel(const float* __restrict__ qkv, float* __restrict__ attn)
{
    int h = blockIdx.x;
    int tid = threadIdx.x;  // 256
    __shared__ float sl[NTOK];
    __shared__ float qs[DH];
    __shared__ float red[8];

    if (tid < DH) qs[tid] = ASCALE * qkv[h * DH + tid];
    __syncthreads();

    float lmax = -1e30f;
    for (int j = tid; j < NTOK; j += 256) {
        const float* kb = qkv + (size_t)j * QKVW + 512 + h * DH;
        float s = 0.f;
#pragma unroll
        for (int d = 0; d < DH; d++) s += qs[d] * kb[d];
        sl[j] = s;
        lmax = fmaxf(lmax, s);
    }
#pragma unroll
    for (int o = 16; o; o >>= 1) lmax = fmaxf(lmax, __shfl_xor_sync(0xffffffffu, lmax, o));
    if ((tid & 31) == 0) red[tid >> 5] = lmax;
    __syncthreads();
    if (tid == 0) { float m = red[0]; for (int i = 1; i < 8; i++) m = fmaxf(m, red[i]); red[0] = m; }
    __syncthreads();
    float mx = red[0];
    __syncthreads();

    float lsum = 0.f;
    for (int j = tid; j < NTOK; j += 256) {
        float e = expf(sl[j] - mx);
        sl[j] = e;
        lsum += e;
    }
#pragma unroll
    for (int o = 16; o; o >>= 1) lsum += __shfl_xor_sync(0xffffffffu, lsum, o);
    if ((tid & 31) == 0) red[tid >> 5] = lsum;
    __syncthreads();
    if (tid == 0) { float t = 0; for (int i = 0; i < 8; i++) t += red[i]; red[0] = t; }
    __syncthreads();
    float inv = 1.f / red[0];

    if (tid < DH) {
        float acc = 0.f;
        for (int j = 0; j < NTOK; j++)
            acc += sl[j] * qkv[(size_t)j * QKVW + 1024 + h * DH + tid];
        attn[h * DH + tid] = acc * inv;   // row 0 (cls) of merged attention out
    }
}

// ---------------------------------------------------------------- time attention
// One warp per (head, nn, f) query; 5 keys: cls + same-nn token in each frame.
__global__ void time_attn_kernel(const float* __restrict__ qkv, float* __restrict__ attn)
{
    int w = (blockIdx.x * blockDim.x + threadIdx.x) >> 5;
    int lane = threadIdx.x & 31;
    if (w >= NHEAD * NSP * FRAMES) return;
    int h = w / (NSP * FRAMES);
    int rem = w % (NSP * FRAMES);
    int nn = rem / FRAMES;
    int f  = rem % FRAMES;
    int qt = 1 + f * NSP + nn;

    const float* qb = qkv + (size_t)qt * QKVW + h * DH;
    float q0 = ASCALE * qb[lane], q1 = ASCALE * qb[lane + 32];

    int kt[5] = {0, 1 + nn, 1 + NSP + nn, 1 + 2 * NSP + nn, 1 + 3 * NSP + nn};
    float lg[5];
#pragma unroll
    for (int j = 0; j < 5; j++) {
        const float* kb = qkv + (size_t)kt[j] * QKVW + 512 + h * DH;
        float p = q0 * kb[lane] + q1 * kb[lane + 32];
#pragma unroll
        for (int o = 16; o; o >>= 1) p += __shfl_xor_sync(0xffffffffu, p, o);
        lg[j] = p;
    }
    float m = lg[0];
#pragma unroll
    for (int j = 1; j < 5; j++) m = fmaxf(m, lg[j]);
    float e[5], s = 0.f;
#pragma unroll
    for (int j = 0; j < 5; j++) { e[j] = expf(lg[j] - m); s += e[j]; }
    float inv = 1.f / s;

    float o0 = 0.f, o1 = 0.f;
#pragma unroll
    for (int j = 0; j < 5; j++) {
        const float* vb = qkv + (size_t)kt[j] * QKVW + 1024 + h * DH;
        float p = e[j] * inv;
        o0 += p * vb[lane];
        o1 += p * vb[lane + 32];
    }
    attn[(size_t)qt * D + h * DH + lane]      = o0;
    attn[(size_t)qt * D + h * DH + lane + 32] = o1;
}

// ---------------------------------------------------------------- space attention: scores
// group g = h*8 + f*2 + half; queries = own half (600), keys = cls + other half (601)
__global__ void space_scores_kernel(const float* __restrict__ qkv, float* __restrict__ S)
{
    int g = blockIdx.z;
    int h = g >> 3, f = (g >> 1) & 3, half = g & 1;
    int i0 = blockIdx.x * 64;
    int j0 = blockIdx.y * 64;
    int tid = threadIdx.x;
    int tx = tid & 15, ty = tid >> 4;

    __shared__ float Qs[64][65];
    __shared__ float Ks[64][65];

#pragma unroll
    for (int u = 0; u < 16; u++) {
        int idx = tid + u * 256;
        int r = idx >> 6, d = idx & 63;
        int i = i0 + r;
        float v = 0.f;
        if (i < HALFN) {
            int qt = 1 + f * NSP + half * HALFN + i;
            v = ASCALE * qkv[(size_t)qt * QKVW + h * DH + d];
        }
        Qs[r][d] = v;
    }
#pragma unroll
    for (int u = 0; u < 16; u++) {
        int idx = tid + u * 256;
        int r = idx >> 6, d = idx & 63;
        int j = j0 + r;
        float v = 0.f;
        if (j < NKEY) {
            int kt = (j == 0) ? 0 : 1 + f * NSP + (1 - half) * HALFN + (j - 1);
            v = qkv[(size_t)kt * QKVW + 512 + h * DH + d];
        }
        Ks[r][d] = v;
    }
    __syncthreads();

    float acc[4][4];
#pragma unroll
    for (int a = 0; a < 4; a++)
#pragma unroll
        for (int b = 0; b < 4; b++) acc[a][b] = 0.f;

#pragma unroll
    for (int k = 0; k < 64; k++) {
        float ra[4], rb[4];
#pragma unroll
        for (int a = 0; a < 4; a++) ra[a] = Qs[ty * 4 + a][k];
#pragma unroll
        for (int b = 0; b < 4; b++) rb[b] = Ks[tx * 4 + b][k];
#pragma unroll
        for (int a = 0; a < 4; a++)
#pragma unroll
            for (int b = 0; b < 4; b++) acc[a][b] += ra[a] * rb[b];
    }

#pragma unroll
    for (int a = 0; a < 4; a++) {
        int i = i0 + ty * 4 + a;
        if (i >= HALFN) continue;
#pragma unroll
        for (int b = 0; b < 4; b++) {
            int j = j0 + tx * 4 + b;
            if (j >= NKEY) continue;
            S[(size_t)g * HALFN * NKEY + (size_t)i * NKEY + j] = acc[a][b];
        }
    }
}

// ---------------------------------------------------------------- space attention: softmax rows
__global__ void softmax_kernel(float* __restrict__ S)
{
    int row = blockIdx.x;  // NGRP*HALFN rows
    float* r = S + (size_t)row * NKEY;
    int tid = threadIdx.x;  // 128
    __shared__ float red[4];

    float m = -1e30f;
    for (int j = tid; j < NKEY; j += 128) m = fmaxf(m, r[j]);
#pragma unroll
    for (int o = 16; o; o >>= 1) m = fmaxf(m, __shfl_xor_sync(0xffffffffu, m, o));
    if ((tid & 31) == 0) red[tid >> 5] = m;
    __syncthreads();
    if (tid == 0) { float t = red[0]; for (int i = 1; i < 4; i++) t = fmaxf(t, red[i]); red[0] = t; }
    __syncthreads();
    m = red[0];
    __syncthreads();

    float s = 0.f;
    for (int j = tid; j < NKEY; j += 128) {
        float e = expf(r[j] - m);
        r[j] = e;
        s += e;
    }
#pragma unroll
    for (int o = 16; o; o >>= 1) s += __shfl_xor_sync(0xffffffffu, s, o);
    if ((tid & 31) == 0) red[tid >> 5] = s;
    __syncthreads();
    if (tid == 0) { float t = 0; for (int i = 0; i < 4; i++) t += red[i]; red[0] = t; }
    __syncthreads();
    float inv = 1.f / red[0];
    for (int j = tid; j < NKEY; j += 128) r[j] *= inv;
}

// ---------------------------------------------------------------- space attention: P @ V
__global__ void space_av_kernel(const float* __restrict__ S, const float* __restrict__ qkv,
                                float* __restrict__ attn)
{
    int g = blockIdx.z;
    int h = g >> 3, f = (g >> 1) & 3, half = g & 1;
    int i0 = blockIdx.x * 64;
    int tid = threadIdx.x;
    int tx = tid & 15, ty = tid >> 4;

    __shared__ float Ps[64][65];
    __shared__ float Vs[64][65];

    float acc[4][4];
#pragma unroll
    for (int a = 0; a < 4; a++)
#pragma unroll
        for (int b = 0; b < 4; b++) acc[a][b] = 0.f;

    const float* Srow = S + (size_t)g * HALFN * NKEY;

    for (int j0 = 0; j0 < NKEY; j0 += 64) {
#pragma unroll
        for (int u = 0; u < 16; u++) {
            int idx = tid + u * 256;
            int rr = idx >> 6, cc = idx & 63;
            int i = i0 + rr, j = j0 + cc;
            Ps[rr][cc] = (i < HALFN && j < NKEY) ? Srow[(size_t)i * NKEY + j] : 0.f;
        }
#pragma unroll
        for (int u = 0; u < 16; u++) {
            int idx = tid + u * 256;
            int rr = idx >> 6, dd = idx & 63;
            int j = j0 + rr;
            float v = 0.f;
            if (j < NKEY) {
                int kt = (j == 0) ? 0 : 1 + f * NSP + (1 - half) * HALFN + (j - 1);
                v = qkv[(size_t)kt * QKVW + 1024 + h * DH + dd];
            }
            Vs[rr][dd] = v;
        }
        __syncthreads();
#pragma unroll
        for (int k = 0; k < 64; k++) {
            float ra[4], rb[4];
#pragma unroll
            for (int a = 0; a < 4; a++) ra[a] = Ps[ty * 4 + a][k];
#pragma unroll
            for (int b = 0; b < 4; b++) rb[b] = Vs[k][tx * 4 + b];
#pragma unroll
            for (int a = 0; a < 4; a++)
#pragma unroll
                for (int b = 0; b < 4; b++) acc[a][b] += ra[a] * rb[b];
        }
        __syncthreads();
    }

#pragma unroll
    for (int a = 0; a < 4; a++) {
        int i = i0 + ty * 4 + a;
        if (i >= HALFN) continue;
        int qt = 1 + f * NSP + half * HALFN + i;
#pragma unroll
        for (int b = 0; b < 4; b++)
            attn[(size_t)qt * D + h * DH + tx * 4 + b] = acc[a][b];
    }
}

// ---------------------------------------------------------------- GEGLU activation
__global__ void geglu_kernel(const float* __restrict__ h, float* __restrict__ act)
{
    int idx = blockIdx.x * blockDim.x + threadIdx.x;
    if (idx >= NTOK * FF2) return;
    int t = idx / FF2, j = idx % FF2;
    float u = h[(size_t)t * FF1 + j];
    float g = h[(size_t)t * FF1 + FF2 + j];
    float ge = 0.5f * g * (1.f + erff(g * 0.70710678118654752f));
    act[idx] = u * ge;
}

// ---------------------------------------------------------------- classifier head
__global__ void head_kernel(const float* __restrict__ xn, const float* __restrict__ ow,
                            const float* __restrict__ ob, float* __restrict__ out)
{
    int tid = threadIdx.x;
    if (tid >= 60) return;
    float s = ob[tid];
    for (int d = 0; d < D; d++) s += xn[d] * ow[d * 60 + tid];
    out[tid] = s;
}

}  // namespace

extern "C" void kernel_launch(void* const* d_in, const int* in_sizes, int n_in,
                              void* d_out, int out_size)
{
    const float* video   = (const float*)d_in[0];
    const float* patch_w = (const float*)d_in[1];
    const float* patch_b = (const float*)d_in[2];
    const float* pos_emb = (const float*)d_in[3];
    const float* cls_tok = (const float*)d_in[4];
    const float* t_ln_g  = (const float*)d_in[5];
    const float* t_ln_b  = (const float*)d_in[6];
    const float* t_qkv_w = (const float*)d_in[7];
    const float* t_out_w = (const float*)d_in[8];
    const float* t_out_b = (const float*)d_in[9];
    const float* s_ln_g  = (const float*)d_in[10];
    const float* s_ln_b  = (const float*)d_in[11];
    const float* s_qkv_w = (const float*)d_in[12];
    const float* s_out_w = (const float*)d_in[13];
    const float* s_out_b = (const float*)d_in[14];
    const float* f_ln_g  = (const float*)d_in[15];
    const float* f_ln_b  = (const float*)d_in[16];
    const float* f_w1    = (const float*)d_in[17];
    const float* f_b1    = (const float*)d_in[18];
    const float* f_w2    = (const float*)d_in[19];
    const float* f_b2    = (const float*)d_in[20];
    const float* o_ln_g  = (const float*)d_in[21];
    const float* o_ln_b  = (const float*)d_in[22];
    const float* o_w     = (const float*)d_in[23];
    const float* o_b     = (const float*)d_in[24];
    float* out = (float*)d_out;

    float *x, *xn, *attn, *qkv, *tok, *hbuf, *act, *S;
    cudaGetSymbolAddress((void**)&x,    g_x);
    cudaGetSymbolAddress((void**)&xn,   g_xn);
    cudaGetSymbolAddress((void**)&attn, g_attn);
    cudaGetSymbolAddress((void**)&qkv,  g_qkv);
    cudaGetSymbolAddress((void**)&tok,  g_tok);
    cudaGetSymbolAddress((void**)&hbuf, g_h);
    cudaGetSymbolAddress((void**)&act,  g_act);
    cudaGetSymbolAddress((void**)&S,    g_S);

    auto gemm = [&](const float* A, const float* B, const float* bias, const float* resid,
                    float* C, int M, int N, int K) {
        dim3 grid((N + 63) / 64, (M + 127) / 128);
        sgemm_kernel<<<grid, 256>>>(A, B, bias, resid, C, M, N, K);
    };

    // ---- patch embed + pos + cls ----
    patchify_kernel<<<(NPATCH * PD + 255) / 256, 256>>>(video, tok);
    gemm(tok, patch_w, patch_b, nullptr, x + D, NPATCH, D, PD);
    addpos_kernel<<<(NTOK * D + 255) / 256, 256>>>(x, cls_tok, pos_emb);

    for (int i = 0; i < 12; i++) {
        // ---------------- time attention ----------------
        layernorm_kernel<<<NTOK, 256>>>(x, t_ln_g + i * D, t_ln_b + i * D, xn, NTOK);
        gemm(xn, t_qkv_w + (size_t)i * D * QKVW, nullptr, nullptr, qkv, NTOK, QKVW, D);
        cls_attn_kernel<<<NHEAD, 256>>>(qkv, attn);
        time_attn_kernel<<<(NHEAD * NSP * FRAMES * 32 + 255) / 256, 256>>>(qkv, attn);
        gemm(attn, t_out_w + (size_t)i * D * D, t_out_b + i * D, x, x, NTOK, D, D);

        // ---------------- space attention ----------------
        layernorm_kernel<<<NTOK, 256>>>(x, s_ln_g + i * D, s_ln_b + i * D, xn, NTOK);
        gemm(xn, s_qkv_w + (size_t)i * D * QKVW, nullptr, nullptr, qkv, NTOK, QKVW, D);
        cls_attn_kernel<<<NHEAD, 256>>>(qkv, attn);
        {
            dim3 gs((HALFN + 63) / 64, (NKEY + 63) / 64, NGRP);
            space_scores_kernel<<<gs, 256>>>(qkv, S);
            softmax_kernel<<<NGRP * HALFN, 128>>>(S);
            dim3 ga((HALFN + 63) / 64, 1, NGRP);
            space_av_kernel<<<ga, 256>>>(S, qkv, attn);
        }
        gemm(attn, s_out_w + (size_t)i * D * D, s_out_b + i * D, x, x, NTOK, D, D);

        // ---------------- GEGLU FF ----------------
        layernorm_kernel<<<NTOK, 256>>>(x, f_ln_g + i * D, f_ln_b + i * D, xn, NTOK);
        gemm(xn, f_w1 + (size_t)i * D * FF1, f_b1 + i * FF1, nullptr, hbuf, NTOK, FF1, D);
        geglu_kernel<<<(NTOK * FF2 + 255) / 256, 256>>>(hbuf, act);
        gemm(act, f_w2 + (size_t)i * FF2 * D, f_b2 + i * D, x, x, NTOK, D, FF2);
    }

    // ---- final LN on cls + head ----
    layernorm_kernel<<<1, 256>>>(x, o_ln_g, o_ln_b, xn, 1);
    head_kernel<<<1, 64>>>(xn, o_w, o_b, out);
}

// round 3
// speedup vs baseline: 1.2472x; 1.2472x over previous
#include <cuda_runtime.h>
#include <math.h>

namespace {

constexpr int NTOK  = 4801;
constexpr int D     = 512;
constexpr int QKVW  = 1536;
constexpr int FRAMES= 4;
constexpr int NSP   = 1200;
constexpr int HALFN = 600;
constexpr int NKEY  = 601;
constexpr int NHEAD = 8;
constexpr int DH    = 64;
constexpr float ASCALE = 0.125f;
constexpr int FF1   = 4096;
constexpr int FF2   = 2048;
constexpr int NPATCH= 4800;
constexpr int PD    = 768;
constexpr int NGRP  = 64;

__device__ float g_x   [NTOK * D];
__device__ float g_xn  [NTOK * D];
__device__ float g_attn[NTOK * D];
__device__ float g_qkv [NTOK * QKVW];
__device__ float g_tok [NPATCH * PD];
__device__ float g_h   [NTOK * FF1];
__device__ float g_act [NTOK * FF2];
__device__ float g_S   [(size_t)NGRP * HALFN * NKEY];

__device__ __forceinline__ unsigned f2tf32(float x) {
    unsigned y;
    asm("cvt.rna.tf32.f32 %0, %1;" : "=r"(y) : "f"(x));
    return y;
}

__device__ __forceinline__ void mma_tf32(float* acc, const unsigned* a, const unsigned* b) {
    asm volatile(
        "mma.sync.aligned.m16n8k8.row.col.f32.tf32.tf32.f32 "
        "{%0,%1,%2,%3}, {%4,%5,%6,%7}, {%8,%9}, {%0,%1,%2,%3};"
        : "+f"(acc[0]), "+f"(acc[1]), "+f"(acc[2]), "+f"(acc[3])
        : "r"(a[0]), "r"(a[1]), "r"(a[2]), "r"(a[3]), "r"(b[0]), "r"(b[1]));
}

// ---------------------------------------------------------------- 3xTF32 GEMM
// C[M,N] = A[M,K] @ B[K,N] (+bias) (+resid). BM=128 BN=128 BK=16.
// 256 threads = 8 warps; warp tile 64x32; split-precision hi/lo -> ~fp32 accuracy.
// Requires: N % 128 == 0, K % 16 == 0. M arbitrary.
__global__ __launch_bounds__(256, 1)
void tgemm_kernel(const float* __restrict__ A, const float* __restrict__ B,
                  const float* __restrict__ bias, const float* __restrict__ resid,
                  float* __restrict__ C, int M, int N, int K)
{
    __shared__ unsigned AsH[128][20], AsL[128][20];
    __shared__ unsigned BsH[16][136], BsL[16][136];

    const int tid  = threadIdx.x;
    const int lane = tid & 31;
    const int warp = tid >> 5;
    const int grp  = lane >> 2;
    const int qid  = lane & 3;
    const int wm   = (warp & 1) * 64;
    const int wn   = (warp >> 1) * 32;
    const int row0 = blockIdx.y * 128;
    const int col0 = blockIdx.x * 128;

    float acc[4][4][4];
#pragma unroll
    for (int mt = 0; mt < 4; mt++)
#pragma unroll
        for (int nt = 0; nt < 4; nt++)
#pragma unroll
            for (int e = 0; e < 4; e++) acc[mt][nt][e] = 0.f;

    for (int k0 = 0; k0 < K; k0 += 16) {
#pragma unroll
        for (int u = 0; u < 2; u++) {
            int idx = tid + u * 256;
            int r = idx >> 2, c4 = (idx & 3) * 4;
            int gr = row0 + r;
            float4 v = (gr < M) ? *reinterpret_cast<const float4*>(A + (size_t)gr * K + k0 + c4)
                                : make_float4(0.f, 0.f, 0.f, 0.f);
            float vv[4] = {v.x, v.y, v.z, v.w};
#pragma unroll
            for (int e = 0; e < 4; e++) {
                unsigned hi = f2tf32(vv[e]);
                AsH[r][c4 + e] = hi;
                AsL[r][c4 + e] = f2tf32(vv[e] - __uint_as_float(hi));
            }
        }
#pragma unroll
        for (int u = 0; u < 2; u++) {
            int idx = tid + u * 256;
            int kr = idx >> 5, c4 = (idx & 31) * 4;
            float4 v = *reinterpret_cast<const float4*>(B + (size_t)(k0 + kr) * N + col0 + c4);
            float vv[4] = {v.x, v.y, v.z, v.w};
#pragma unroll
            for (int e = 0; e < 4; e++) {
                unsigned hi = f2tf32(vv[e]);
                BsH[kr][c4 + e] = hi;
                BsL[kr][c4 + e] = f2tf32(vv[e] - __uint_as_float(hi));
            }
        }
        __syncthreads();

#pragma unroll
        for (int kk = 0; kk < 16; kk += 8) {
            unsigned bh[4][2], bl[4][2];
#pragma unroll
            for (int nt = 0; nt < 4; nt++) {
                int c = wn + nt * 8;
                bh[nt][0] = BsH[kk + qid    ][c + grp];
                bh[nt][1] = BsH[kk + qid + 4][c + grp];
                bl[nt][0] = BsL[kk + qid    ][c + grp];
                bl[nt][1] = BsL[kk + qid + 4][c + grp];
            }
#pragma unroll
            for (int mt = 0; mt < 4; mt++) {
                int r = wm + mt * 16;
                unsigned ah[4], al[4];
                ah[0] = AsH[r + grp    ][kk + qid    ];
                ah[1] = AsH[r + grp + 8][kk + qid    ];
                ah[2] = AsH[r + grp    ][kk + qid + 4];
                ah[3] = AsH[r + grp + 8][kk + qid + 4];
                al[0] = AsL[r + grp    ][kk + qid    ];
                al[1] = AsL[r + grp + 8][kk + qid    ];
                al[2] = AsL[r + grp    ][kk + qid + 4];
                al[3] = AsL[r + grp + 8][kk + qid + 4];
#pragma unroll
                for (int nt = 0; nt < 4; nt++) {
                    mma_tf32(acc[mt][nt], al, bh[nt]);   // lo*hi
                    mma_tf32(acc[mt][nt], ah, bl[nt]);   // hi*lo
                    mma_tf32(acc[mt][nt], ah, bh[nt]);   // hi*hi
                }
            }
        }
        __syncthreads();
    }

#pragma unroll
    for (int mt = 0; mt < 4; mt++) {
#pragma unroll
        for (int e2 = 0; e2 < 2; e2++) {
            int gr = row0 + wm + mt * 16 + grp + e2 * 8;
            if (gr >= M) continue;
#pragma unroll
            for (int nt = 0; nt < 4; nt++) {
                int gc = col0 + wn + nt * 8 + qid * 2;
                float v0 = acc[mt][nt][e2 * 2 + 0];
                float v1 = acc[mt][nt][e2 * 2 + 1];
                if (bias)  { v0 += bias[gc]; v1 += bias[gc + 1]; }
                if (resid) {
                    v0 += resid[(size_t)gr * N + gc];
                    v1 += resid[(size_t)gr * N + gc + 1];
                }
                C[(size_t)gr * N + gc]     = v0;
                C[(size_t)gr * N + gc + 1] = v1;
            }
        }
    }
}

// ---------------------------------------------------------------- patchify
__global__ void patchify_kernel(const float* __restrict__ video, float* __restrict__ tok)
{
    int idx = blockIdx.x * blockDim.x + threadIdx.x;
    if (idx >= NPATCH * PD) return;
    int t = idx / PD, pd = idx % PD;
    int side = t / 2400;
    int r = t % 2400;
    int f = r / 600;
    int rr = r % 600;
    int ph = rr / 20;
    int pw = rr % 20;
    int p1 = pd / 48;
    int rem = pd % 48;
    int p2 = rem / 3;
    int c  = rem % 3;
    int row = ph * 16 + p1;
    int col = side * 320 + pw * 16 + p2;
    tok[idx] = video[(((size_t)f * 3 + c) * 480 + row) * 640 + col];
}

__global__ void addpos_kernel(float* __restrict__ x, const float* __restrict__ cls,
                              const float* __restrict__ pos)
{
    int idx = blockIdx.x * blockDim.x + threadIdx.x;
    if (idx >= NTOK * D) return;
    if (idx < D) x[idx] = cls[idx] + pos[idx];
    else         x[idx] += pos[idx];
}

// ---------------------------------------------------------------- LayerNorm
__global__ void layernorm_kernel(const float* __restrict__ x, const float* __restrict__ g,
                                 const float* __restrict__ b, float* __restrict__ out, int M)
{
    int row = blockIdx.x;
    if (row >= M) return;
    int tid = threadIdx.x;  // 256
    const float* xr = x + (size_t)row * D;
    float x0 = xr[tid], x1 = xr[tid + 256];
    __shared__ float red[8];

    float s = x0 + x1;
#pragma unroll
    for (int o = 16; o; o >>= 1) s += __shfl_xor_sync(0xffffffffu, s, o);
    if ((tid & 31) == 0) red[tid >> 5] = s;
    __syncthreads();
    if (tid == 0) { float t = 0; for (int i = 0; i < 8; i++) t += red[i]; red[0] = t; }
    __syncthreads();
    float mu = red[0] * (1.f / 512.f);
    __syncthreads();

    float d0 = x0 - mu, d1 = x1 - mu;
    float v = d0 * d0 + d1 * d1;
#pragma unroll
    for (int o = 16; o; o >>= 1) v += __shfl_xor_sync(0xffffffffu, v, o);
    if ((tid & 31) == 0) red[tid >> 5] = v;
    __syncthreads();
    if (tid == 0) { float t = 0; for (int i = 0; i < 8; i++) t += red[i]; red[0] = t; }
    __syncthreads();
    float rstd = rsqrtf(red[0] * (1.f / 512.f) + 1e-5f);

    out[(size_t)row * D + tid]       = d0 * rstd * g[tid] + b[tid];
    out[(size_t)row * D + tid + 256] = d1 * rstd * g[tid + 256] + b[tid + 256];
}

// ---------------------------------------------------------------- cls attention
__global__ void cls_attn_kernel(const float* __restrict__ qkv, float* __restrict__ attn)
{
    int h = blockIdx.x;
    int tid = threadIdx.x;  // 256
    __shared__ float sl[NTOK];
    __shared__ float qs[DH];
    __shared__ float red[8];
    __shared__ float part[4][DH];

    if (tid < DH) qs[tid] = ASCALE * qkv[h * DH + tid];
    __syncthreads();

    float lmax = -1e30f;
    for (int j = tid; j < NTOK; j += 256) {
        const float* kb = qkv + (size_t)j * QKVW + 512 + h * DH;
        float s = 0.f;
#pragma unroll
        for (int d = 0; d < DH; d++) s += qs[d] * kb[d];
        sl[j] = s;
        lmax = fmaxf(lmax, s);
    }
#pragma unroll
    for (int o = 16; o; o >>= 1) lmax = fmaxf(lmax, __shfl_xor_sync(0xffffffffu, lmax, o));
    if ((tid & 31) == 0) red[tid >> 5] = lmax;
    __syncthreads();
    if (tid == 0) { float m = red[0]; for (int i = 1; i < 8; i++) m = fmaxf(m, red[i]); red[0] = m; }
    __syncthreads();
    float mx = red[0];
    __syncthreads();

    float lsum = 0.f;
    for (int j = tid; j < NTOK; j += 256) {
        float e = expf(sl[j] - mx);
        sl[j] = e;
        lsum += e;
    }
#pragma unroll
    for (int o = 16; o; o >>= 1) lsum += __shfl_xor_sync(0xffffffffu, lsum, o);
    if ((tid & 31) == 0) red[tid >> 5] = lsum;
    __syncthreads();
    if (tid == 0) { float t = 0; for (int i = 0; i < 8; i++) t += red[i]; red[0] = t; }
    __syncthreads();
    float inv = 1.f / red[0];
    __syncthreads();

    int gi = tid >> 6, d = tid & 63;
    float acc = 0.f;
    for (int j = gi; j < NTOK; j += 4)
        acc += sl[j] * qkv[(size_t)j * QKVW + 1024 + h * DH + d];
    part[gi][d] = acc;
    __syncthreads();
    if (tid < DH)
        attn[h * DH + tid] = (part[0][tid] + part[1][tid] + part[2][tid] + part[3][tid]) * inv;
}

// ---------------------------------------------------------------- time attention
__global__ void time_attn_kernel(const float* __restrict__ qkv, float* __restrict__ attn)
{
    int w = (blockIdx.x * blockDim.x + threadIdx.x) >> 5;
    int lane = threadIdx.x & 31;
    if (w >= NHEAD * NSP * FRAMES) return;
    int h = w / (NSP * FRAMES);
    int rem = w % (NSP * FRAMES);
    int nn = rem / FRAMES;
    int f  = rem % FRAMES;
    int qt = 1 + f * NSP + nn;

    const float* qb = qkv + (size_t)qt * QKVW + h * DH;
    float q0 = ASCALE * qb[lane], q1 = ASCALE * qb[lane + 32];

    int kt[5] = {0, 1 + nn, 1 + NSP + nn, 1 + 2 * NSP + nn, 1 + 3 * NSP + nn};
    float lg[5];
#pragma unroll
    for (int j = 0; j < 5; j++) {
        const float* kb = qkv + (size_t)kt[j] * QKVW + 512 + h * DH;
        float p = q0 * kb[lane] + q1 * kb[lane + 32];
#pragma unroll
        for (int o = 16; o; o >>= 1) p += __shfl_xor_sync(0xffffffffu, p, o);
        lg[j] = p;
    }
    float m = lg[0];
#pragma unroll
    for (int j = 1; j < 5; j++) m = fmaxf(m, lg[j]);
    float e[5], s = 0.f;
#pragma unroll
    for (int j = 0; j < 5; j++) { e[j] = expf(lg[j] - m); s += e[j]; }
    float inv = 1.f / s;

    float o0 = 0.f, o1 = 0.f;
#pragma unroll
    for (int j = 0; j < 5; j++) {
        const float* vb = qkv + (size_t)kt[j] * QKVW + 1024 + h * DH;
        float p = e[j] * inv;
        o0 += p * vb[lane];
        o1 += p * vb[lane + 32];
    }
    attn[(size_t)qt * D + h * DH + lane]      = o0;
    attn[(size_t)qt * D + h * DH + lane + 32] = o1;
}

// ---------------------------------------------------------------- space attention: scores
__global__ void space_scores_kernel(const float* __restrict__ qkv, float* __restrict__ S)
{
    int g = blockIdx.z;
    int h = g >> 3, f = (g >> 1) & 3, half = g & 1;
    int i0 = blockIdx.x * 64;
    int j0 = blockIdx.y * 64;
    int tid = threadIdx.x;
    int tx = tid & 15, ty = tid >> 4;

    __shared__ float Qs[64][65];
    __shared__ float Ks[64][65];

#pragma unroll
    for (int u = 0; u < 16; u++) {
        int idx = tid + u * 256;
        int r = idx >> 6, d = idx & 63;
        int i = i0 + r;
        float v = 0.f;
        if (i < HALFN) {
            int qt = 1 + f * NSP + half * HALFN + i;
            v = ASCALE * qkv[(size_t)qt * QKVW + h * DH + d];
        }
        Qs[r][d] = v;
    }
#pragma unroll
    for (int u = 0; u < 16; u++) {
        int idx = tid + u * 256;
        int r = idx >> 6, d = idx & 63;
        int j = j0 + r;
        float v = 0.f;
        if (j < NKEY) {
            int kt = (j == 0) ? 0 : 1 + f * NSP + (1 - half) * HALFN + (j - 1);
            v = qkv[(size_t)kt * QKVW + 512 + h * DH + d];
        }
        Ks[r][d] = v;
    }
    __syncthreads();

    float acc[4][4];
#pragma unroll
    for (int a = 0; a < 4; a++)
#pragma unroll
        for (int b = 0; b < 4; b++) acc[a][b] = 0.f;

#pragma unroll
    for (int k = 0; k < 64; k++) {
        float ra[4], rb[4];
#pragma unroll
        for (int a = 0; a < 4; a++) ra[a] = Qs[ty * 4 + a][k];
#pragma unroll
        for (int b = 0; b < 4; b++) rb[b] = Ks[tx * 4 + b][k];
#pragma unroll
        for (int a = 0; a < 4; a++)
#pragma unroll
            for (int b = 0; b < 4; b++) acc[a][b] += ra[a] * rb[b];
    }

#pragma unroll
    for (int a = 0; a < 4; a++) {
        int i = i0 + ty * 4 + a;
        if (i >= HALFN) continue;
#pragma unroll
        for (int b = 0; b < 4; b++) {
            int j = j0 + tx * 4 + b;
            if (j >= NKEY) continue;
            S[(size_t)g * HALFN * NKEY + (size_t)i * NKEY + j] = acc[a][b];
        }
    }
}

// ---------------------------------------------------------------- softmax rows
__global__ void softmax_kernel(float* __restrict__ S)
{
    int row = blockIdx.x;
    float* r = S + (size_t)row * NKEY;
    int tid = threadIdx.x;  // 128
    __shared__ float red[4];

    float m = -1e30f;
    for (int j = tid; j < NKEY; j += 128) m = fmaxf(m, r[j]);
#pragma unroll
    for (int o = 16; o; o >>= 1) m = fmaxf(m, __shfl_xor_sync(0xffffffffu, m, o));
    if ((tid & 31) == 0) red[tid >> 5] = m;
    __syncthreads();
    if (tid == 0) { float t = red[0]; for (int i = 1; i < 4; i++) t = fmaxf(t, red[i]); red[0] = t; }
    __syncthreads();
    m = red[0];
    __syncthreads();

    float s = 0.f;
    for (int j = tid; j < NKEY; j += 128) {
        float e = expf(r[j] - m);
        r[j] = e;
        s += e;
    }
#pragma unroll
    for (int o = 16; o; o >>= 1) s += __shfl_xor_sync(0xffffffffu, s, o);
    if ((tid & 31) == 0) red[tid >> 5] = s;
    __syncthreads();
    if (tid == 0) { float t = 0; for (int i = 0; i < 4; i++) t += red[i]; red[0] = t; }
    __syncthreads();
    float inv = 1.f / red[0];
    for (int j = tid; j < NKEY; j += 128) r[j] *= inv;
}

// ---------------------------------------------------------------- space attention: P @ V
__global__ void space_av_kernel(const float* __restrict__ S, const float* __restrict__ qkv,
                                float* __restrict__ attn)
{
    int g = blockIdx.z;
    int h = g >> 3, f = (g >> 1) & 3, half = g & 1;
    int i0 = blockIdx.x * 64;
    int tid = threadIdx.x;
    int tx = tid & 15, ty = tid >> 4;

    __shared__ float Ps[64][65];
    __shared__ float Vs[64][65];

    float acc[4][4];
#pragma unroll
    for (int a = 0; a < 4; a++)
#pragma unroll
        for (int b = 0; b < 4; b++) acc[a][b] = 0.f;

    const float* Srow = S + (size_t)g * HALFN * NKEY;

    for (int j0 = 0; j0 < NKEY; j0 += 64) {
#pragma unroll
        for (int u = 0; u < 16; u++) {
            int idx = tid + u * 256;
            int rr = idx >> 6, cc = idx & 63;
            int i = i0 + rr, j = j0 + cc;
            Ps[rr][cc] = (i < HALFN && j < NKEY) ? Srow[(size_t)i * NKEY + j] : 0.f;
        }
#pragma unroll
        for (int u = 0; u < 16; u++) {
            int idx = tid + u * 256;
            int rr = idx >> 6, dd = idx & 63;
            int j = j0 + rr;
            float v = 0.f;
            if (j < NKEY) {
                int kt = (j == 0) ? 0 : 1 + f * NSP + (1 - half) * HALFN + (j - 1);
                v = qkv[(size_t)kt * QKVW + 1024 + h * DH + dd];
            }
            Vs[rr][dd] = v;
        }
        __syncthreads();
#pragma unroll
        for (int k = 0; k < 64; k++) {
            float ra[4], rb[4];
#pragma unroll
            for (int a = 0; a < 4; a++) ra[a] = Ps[ty * 4 + a][k];
#pragma unroll
            for (int b = 0; b < 4; b++) rb[b] = Vs[k][tx * 4 + b];
#pragma unroll
            for (int a = 0; a < 4; a++)
#pragma unroll
                for (int b = 0; b < 4; b++) acc[a][b] += ra[a] * rb[b];
        }
        __syncthreads();
    }

#pragma unroll
    for (int a = 0; a < 4; a++) {
        int i = i0 + ty * 4 + a;
        if (i >= HALFN) continue;
        int qt = 1 + f * NSP + half * HALFN + i;
#pragma unroll
        for (int b = 0; b < 4; b++)
            attn[(size_t)qt * D + h * DH + tx * 4 + b] = acc[a][b];
    }
}

// ---------------------------------------------------------------- GEGLU
__global__ void geglu_kernel(const float* __restrict__ h, float* __restrict__ act)
{
    int idx = blockIdx.x * blockDim.x + threadIdx.x;
    if (idx >= NTOK * FF2) return;
    int t = idx / FF2, j = idx % FF2;
    float u = h[(size_t)t * FF1 + j];
    float g = h[(size_t)t * FF1 + FF2 + j];
    float ge = 0.5f * g * (1.f + erff(g * 0.70710678118654752f));
    act[idx] = u * ge;
}

// ---------------------------------------------------------------- head
__global__ void head_kernel(const float* __restrict__ xn, const float* __restrict__ ow,
                            const float* __restrict__ ob, float* __restrict__ out)
{
    int tid = threadIdx.x;
    if (tid >= 60) return;
    float s = ob[tid];
    for (int d = 0; d < D; d++) s += xn[d] * ow[d * 60 + tid];
    out[tid] = s;
}

}  // namespace

extern "C" void kernel_launch(void* const* d_in, const int* in_sizes, int n_in,
                              void* d_out, int out_size)
{
    const float* video   = (const float*)d_in[0];
    const float* patch_w = (const float*)d_in[1];
    const float* patch_b = (const float*)d_in[2];
    const float* pos_emb = (const float*)d_in[3];
    const float* cls_tok = (const float*)d_in[4];
    const float* t_ln_g  = (const float*)d_in[5];
    const float* t_ln_b  = (const float*)d_in[6];
    const float* t_qkv_w = (const float*)d_in[7];
    const float* t_out_w = (const float*)d_in[8];
    const float* t_out_b = (const float*)d_in[9];
    const float* s_ln_g  = (const float*)d_in[10];
    const float* s_ln_b  = (const float*)d_in[11];
    const float* s_qkv_w = (const float*)d_in[12];
    const float* s_out_w = (const float*)d_in[13];
    const float* s_out_b = (const float*)d_in[14];
    const float* f_ln_g  = (const float*)d_in[15];
    const float* f_ln_b  = (const float*)d_in[16];
    const float* f_w1    = (const float*)d_in[17];
    const float* f_b1    = (const float*)d_in[18];
    const float* f_w2    = (const float*)d_in[19];
    const float* f_b2    = (const float*)d_in[20];
    const float* o_ln_g  = (const float*)d_in[21];
    const float* o_ln_b  = (const float*)d_in[22];
    const float* o_w     = (const float*)d_in[23];
    const float* o_b     = (const float*)d_in[24];
    float* out = (float*)d_out;

    float *x, *xn, *attn, *qkv, *tok, *hbuf, *act, *S;
    cudaGetSymbolAddress((void**)&x,    g_x);
    cudaGetSymbolAddress((void**)&xn,   g_xn);
    cudaGetSymbolAddress((void**)&attn, g_attn);
    cudaGetSymbolAddress((void**)&qkv,  g_qkv);
    cudaGetSymbolAddress((void**)&tok,  g_tok);
    cudaGetSymbolAddress((void**)&hbuf, g_h);
    cudaGetSymbolAddress((void**)&act,  g_act);
    cudaGetSymbolAddress((void**)&S,    g_S);

    auto gemm = [&](const float* A, const float* B, const float* bias, const float* resid,
                    float* C, int M, int N, int K) {
        dim3 grid(N / 128, (M + 127) / 128);
        tgemm_kernel<<<grid, 256>>>(A, B, bias, resid, C, M, N, K);
    };

    // ---- patch embed + pos + cls ----
    patchify_kernel<<<(NPATCH * PD + 255) / 256, 256>>>(video, tok);
    gemm(tok, patch_w, patch_b, nullptr, x + D, NPATCH, D, PD);
    addpos_kernel<<<(NTOK * D + 255) / 256, 256>>>(x, cls_tok, pos_emb);

    for (int i = 0; i < 12; i++) {
        // ---------------- time attention ----------------
        layernorm_kernel<<<NTOK, 256>>>(x, t_ln_g + i * D, t_ln_b + i * D, xn, NTOK);
        gemm(xn, t_qkv_w + (size_t)i * D * QKVW, nullptr, nullptr, qkv, NTOK, QKVW, D);
        cls_attn_kernel<<<NHEAD, 256>>>(qkv, attn);
        time_attn_kernel<<<(NHEAD * NSP * FRAMES * 32 + 255) / 256, 256>>>(qkv, attn);
        gemm(attn, t_out_w + (size_t)i * D * D, t_out_b + i * D, x, x, NTOK, D, D);

        // ---------------- space attention ----------------
        layernorm_kernel<<<NTOK, 256>>>(x, s_ln_g + i * D, s_ln_b + i * D, xn, NTOK);
        gemm(xn, s_qkv_w + (size_t)i * D * QKVW, nullptr, nullptr, qkv, NTOK, QKVW, D);
        cls_attn_kernel<<<NHEAD, 256>>>(qkv, attn);
        {
            dim3 gs((HALFN + 63) / 64, (NKEY + 63) / 64, NGRP);
            space_scores_kernel<<<gs, 256>>>(qkv, S);
            softmax_kernel<<<NGRP * HALFN, 128>>>(S);
            dim3 ga((HALFN + 63) / 64, 1, NGRP);
            space_av_kernel<<<ga, 256>>>(S, qkv, attn);
        }
        gemm(attn, s_out_w + (size_t)i * D * D, s_out_b + i * D, x, x, NTOK, D, D);

        // ---------------- GEGLU FF ----------------
        layernorm_kernel<<<NTOK, 256>>>(x, f_ln_g + i * D, f_ln_b + i * D, xn, NTOK);
        gemm(xn, f_w1 + (size_t)i * D * FF1, f_b1 + i * FF1, nullptr, hbuf, NTOK, FF1, D);
        geglu_kernel<<<(NTOK * FF2 + 255) / 256, 256>>>(hbuf, act);
        gemm(act, f_w2 + (size_t)i * FF2 * D, f_b2 + i * D, x, x, NTOK, D, FF2);
    }

    // ---- final LN on cls + head ----
    layernorm_kernel<<<1, 256>>>(x, o_ln_g, o_ln_b, xn, 1);
    head_kernel<<<1, 64>>>(xn, o_w, o_b, out);
}

// round 4
// speedup vs baseline: 1.7614x; 1.4123x over previous
#include <cuda_runtime.h>
#include <cuda_bf16.h>
#include <math.h>

namespace {

constexpr int NTOK  = 4801;
constexpr int D     = 512;
constexpr int QKVW  = 1536;
constexpr int FRAMES= 4;
constexpr int NSP   = 1200;
constexpr int HALFN = 600;
constexpr int NKEY  = 601;
constexpr int NHEAD = 8;
constexpr int DH    = 64;
constexpr float ASCALE = 0.125f;
constexpr int FF1   = 4096;
constexpr int FF2   = 2048;
constexpr int NPATCH= 4800;
constexpr int PD    = 768;
constexpr int NGRP  = 64;

__device__ float g_x   [NTOK * D];
__device__ float g_xn  [NTOK * D];
__device__ float g_attn[NTOK * D];
__device__ float g_qkv [NTOK * QKVW];
__device__ float g_tok [NPATCH * PD];
__device__ float g_h   [NTOK * FF1];
__device__ float g_act [NTOK * FF2];
__device__ float g_S   [(size_t)NGRP * HALFN * NKEY];

// split a pair of floats into packed bf16 hi / lo (2-term decomposition)
__device__ __forceinline__ void split2(float x0, float x1, unsigned& hi, unsigned& lo) {
    __nv_bfloat16 h0 = __float2bfloat16(x0);
    __nv_bfloat16 h1 = __float2bfloat16(x1);
    __nv_bfloat16 l0 = __float2bfloat16(x0 - __bfloat162float(h0));
    __nv_bfloat16 l1 = __float2bfloat16(x1 - __bfloat162float(h1));
    __nv_bfloat162 H = __nv_bfloat162(h0, h1);
    __nv_bfloat162 L = __nv_bfloat162(l0, l1);
    hi = *reinterpret_cast<unsigned*>(&H);
    lo = *reinterpret_cast<unsigned*>(&L);
}

__device__ __forceinline__ void mma_bf16(float* acc, const unsigned* a, const unsigned* b) {
    asm volatile(
        "mma.sync.aligned.m16n8k16.row.col.f32.bf16.bf16.f32 "
        "{%0,%1,%2,%3}, {%4,%5,%6,%7}, {%8,%9}, {%0,%1,%2,%3};"
        : "+f"(acc[0]), "+f"(acc[1]), "+f"(acc[2]), "+f"(acc[3])
        : "r"(a[0]), "r"(a[1]), "r"(a[2]), "r"(a[3]), "r"(b[0]), "r"(b[1]));
}

// ---------------------------------------------------------------- split-bf16 GEMM
// C[M,N] = A[M,K] @ B[K,N] (+bias) (+resid). BM=128 BN=128 BK=32.
// 256 threads = 8 warps; warp tile 64x32; hi/lo split -> ~fp32 accuracy.
// Requires: N % 128 == 0, K % 32 == 0. M arbitrary.
__global__ __launch_bounds__(256)
void tgemm_kernel(const float* __restrict__ A, const float* __restrict__ B,
                  const float* __restrict__ bias, const float* __restrict__ resid,
                  float* __restrict__ C, int M, int N, int K)
{
    // bf162 elements (packed pairs along k). 16 used cols (=32 k) per row.
    __shared__ unsigned AsH[128][20], AsL[128][20];
    __shared__ unsigned BsH[16][136], BsL[16][136];

    const int tid  = threadIdx.x;
    const int lane = tid & 31;
    const int warp = tid >> 5;
    const int grp  = lane >> 2;
    const int qid  = lane & 3;
    const int wm   = (warp & 1) * 64;
    const int wn   = (warp >> 1) * 32;
    const int row0 = blockIdx.y * 128;
    const int col0 = blockIdx.x * 128;

    float acc[4][4][4];
#pragma unroll
    for (int mt = 0; mt < 4; mt++)
#pragma unroll
        for (int nt = 0; nt < 4; nt++)
#pragma unroll
            for (int e = 0; e < 4; e++) acc[mt][nt][e] = 0.f;

    float4 aS[4], b0S[2], b1S[2];

    auto gload = [&](int k0) {
#pragma unroll
        for (int u = 0; u < 4; u++) {
            int idx = tid + u * 256;           // 0..1023
            int r = idx >> 3, f4 = idx & 7;    // row, float4-within-row (32 k)
            int gr = row0 + r;
            aS[u] = (gr < M) ? *reinterpret_cast<const float4*>(A + (size_t)gr * K + k0 + f4 * 4)
                             : make_float4(0.f, 0.f, 0.f, 0.f);
        }
#pragma unroll
        for (int u = 0; u < 2; u++) {
            int idx = tid + u * 256;           // 0..511
            int kp = idx >> 5, c4 = idx & 31;  // k-pair, float4-col
            const float* bp = B + (size_t)(k0 + 2 * kp) * N + col0 + c4 * 4;
            b0S[u] = *reinterpret_cast<const float4*>(bp);
            b1S[u] = *reinterpret_cast<const float4*>(bp + N);
        }
    };

    auto sstore = [&]() {
#pragma unroll
        for (int u = 0; u < 4; u++) {
            int idx = tid + u * 256;
            int r = idx >> 3, f4 = idx & 7;
            unsigned h0, l0, h1, l1;
            split2(aS[u].x, aS[u].y, h0, l0);
            split2(aS[u].z, aS[u].w, h1, l1);
            AsH[r][f4 * 2]     = h0;  AsL[r][f4 * 2]     = l0;
            AsH[r][f4 * 2 + 1] = h1;  AsL[r][f4 * 2 + 1] = l1;
        }
#pragma unroll
        for (int u = 0; u < 2; u++) {
            int idx = tid + u * 256;
            int kp = idx >> 5, c4 = idx & 31;
            float r0[4] = {b0S[u].x, b0S[u].y, b0S[u].z, b0S[u].w};
            float r1[4] = {b1S[u].x, b1S[u].y, b1S[u].z, b1S[u].w};
#pragma unroll
            for (int e = 0; e < 4; e++) {
                unsigned h, l;
                split2(r0[e], r1[e], h, l);    // pack (k=2kp, 2kp+1) for this column
                BsH[kp][c4 * 4 + e] = h;
                BsL[kp][c4 * 4 + e] = l;
            }
        }
    };

    auto compute = [&]() {
#pragma unroll
        for (int kk = 0; kk < 2; kk++) {       // two k16 steps per BK=32
            unsigned bh[4][2], bl[4][2];
#pragma unroll
            for (int nt = 0; nt < 4; nt++) {
                int c = wn + nt * 8 + grp;
                bh[nt][0] = BsH[kk * 8 + qid    ][c];
                bh[nt][1] = BsH[kk * 8 + qid + 4][c];
                bl[nt][0] = BsL[kk * 8 + qid    ][c];
                bl[nt][1] = BsL[kk * 8 + qid + 4][c];
            }
#pragma unroll
            for (int mt = 0; mt < 4; mt++) {
                int r = wm + mt * 16;
                unsigned ah[4], al[4];
                ah[0] = AsH[r + grp    ][kk * 8 + qid    ];
                ah[1] = AsH[r + grp + 8][kk * 8 + qid    ];
                ah[2] = AsH[r + grp    ][kk * 8 + qid + 4];
                ah[3] = AsH[r + grp + 8][kk * 8 + qid + 4];
                al[0] = AsL[r + grp    ][kk * 8 + qid    ];
                al[1] = AsL[r + grp + 8][kk * 8 + qid    ];
                al[2] = AsL[r + grp    ][kk * 8 + qid + 4];
                al[3] = AsL[r + grp + 8][kk * 8 + qid + 4];
#pragma unroll
                for (int nt = 0; nt < 4; nt++) {
                    mma_bf16(acc[mt][nt], al, bh[nt]);   // lo*hi
                    mma_bf16(acc[mt][nt], ah, bl[nt]);   // hi*lo
                    mma_bf16(acc[mt][nt], ah, bh[nt]);   // hi*hi
                }
            }
        }
    };

    gload(0);
    sstore();
    __syncthreads();
    for (int k0 = 32; k0 < K; k0 += 32) {
        gload(k0);          // next tile's global loads in flight during compute
        compute();
        __syncthreads();
        sstore();
        __syncthreads();
    }
    compute();

    // epilogue (C layout identical to k8 variant)
#pragma unroll
    for (int mt = 0; mt < 4; mt++) {
#pragma unroll
        for (int e2 = 0; e2 < 2; e2++) {
            int gr = row0 + wm + mt * 16 + grp + e2 * 8;
            if (gr >= M) continue;
#pragma unroll
            for (int nt = 0; nt < 4; nt++) {
                int gc = col0 + wn + nt * 8 + qid * 2;
                float v0 = acc[mt][nt][e2 * 2 + 0];
                float v1 = acc[mt][nt][e2 * 2 + 1];
                if (bias)  { v0 += bias[gc]; v1 += bias[gc + 1]; }
                if (resid) {
                    v0 += resid[(size_t)gr * N + gc];
                    v1 += resid[(size_t)gr * N + gc + 1];
                }
                C[(size_t)gr * N + gc]     = v0;
                C[(size_t)gr * N + gc + 1] = v1;
            }
        }
    }
}

// ---------------------------------------------------------------- patchify
__global__ void patchify_kernel(const float* __restrict__ video, float* __restrict__ tok)
{
    int idx = blockIdx.x * blockDim.x + threadIdx.x;
    if (idx >= NPATCH * PD) return;
    int t = idx / PD, pd = idx % PD;
    int side = t / 2400;
    int r = t % 2400;
    int f = r / 600;
    int rr = r % 600;
    int ph = rr / 20;
    int pw = rr % 20;
    int p1 = pd / 48;
    int rem = pd % 48;
    int p2 = rem / 3;
    int c  = rem % 3;
    int row = ph * 16 + p1;
    int col = side * 320 + pw * 16 + p2;
    tok[idx] = video[(((size_t)f * 3 + c) * 480 + row) * 640 + col];
}

__global__ void addpos_kernel(float* __restrict__ x, const float* __restrict__ cls,
                              const float* __restrict__ pos)
{
    int idx = blockIdx.x * blockDim.x + threadIdx.x;
    if (idx >= NTOK * D) return;
    if (idx < D) x[idx] = cls[idx] + pos[idx];
    else         x[idx] += pos[idx];
}

// ---------------------------------------------------------------- LayerNorm
__global__ void layernorm_kernel(const float* __restrict__ x, const float* __restrict__ g,
                                 const float* __restrict__ b, float* __restrict__ out, int M)
{
    int row = blockIdx.x;
    if (row >= M) return;
    int tid = threadIdx.x;  // 256
    const float* xr = x + (size_t)row * D;
    float x0 = xr[tid], x1 = xr[tid + 256];
    __shared__ float red[8];

    float s = x0 + x1;
#pragma unroll
    for (int o = 16; o; o >>= 1) s += __shfl_xor_sync(0xffffffffu, s, o);
    if ((tid & 31) == 0) red[tid >> 5] = s;
    __syncthreads();
    if (tid == 0) { float t = 0; for (int i = 0; i < 8; i++) t += red[i]; red[0] = t; }
    __syncthreads();
    float mu = red[0] * (1.f / 512.f);
    __syncthreads();

    float d0 = x0 - mu, d1 = x1 - mu;
    float v = d0 * d0 + d1 * d1;
#pragma unroll
    for (int o = 16; o; o >>= 1) v += __shfl_xor_sync(0xffffffffu, v, o);
    if ((tid & 31) == 0) red[tid >> 5] = v;
    __syncthreads();
    if (tid == 0) { float t = 0; for (int i = 0; i < 8; i++) t += red[i]; red[0] = t; }
    __syncthreads();
    float rstd = rsqrtf(red[0] * (1.f / 512.f) + 1e-5f);

    out[(size_t)row * D + tid]       = d0 * rstd * g[tid] + b[tid];
    out[(size_t)row * D + tid + 256] = d1 * rstd * g[tid + 256] + b[tid + 256];
}

// ---------------------------------------------------------------- cls attention
__global__ void cls_attn_kernel(const float* __restrict__ qkv, float* __restrict__ attn)
{
    int h = blockIdx.x;
    int tid = threadIdx.x;  // 256
    __shared__ float sl[NTOK];
    __shared__ float qs[DH];
    __shared__ float red[8];
    __shared__ float part[4][DH];

    if (tid < DH) qs[tid] = ASCALE * qkv[h * DH + tid];
    __syncthreads();

    float lmax = -1e30f;
    for (int j = tid; j < NTOK; j += 256) {
        const float* kb = qkv + (size_t)j * QKVW + 512 + h * DH;
        float s = 0.f;
#pragma unroll
        for (int d = 0; d < DH; d++) s += qs[d] * kb[d];
        sl[j] = s;
        lmax = fmaxf(lmax, s);
    }
#pragma unroll
    for (int o = 16; o; o >>= 1) lmax = fmaxf(lmax, __shfl_xor_sync(0xffffffffu, lmax, o));
    if ((tid & 31) == 0) red[tid >> 5] = lmax;
    __syncthreads();
    if (tid == 0) { float m = red[0]; for (int i = 1; i < 8; i++) m = fmaxf(m, red[i]); red[0] = m; }
    __syncthreads();
    float mx = red[0];
    __syncthreads();

    float lsum = 0.f;
    for (int j = tid; j < NTOK; j += 256) {
        float e = expf(sl[j] - mx);
        sl[j] = e;
        lsum += e;
    }
#pragma unroll
    for (int o = 16; o; o >>= 1) lsum += __shfl_xor_sync(0xffffffffu, lsum, o);
    if ((tid & 31) == 0) red[tid >> 5] = lsum;
    __syncthreads();
    if (tid == 0) { float t = 0; for (int i = 0; i < 8; i++) t += red[i]; red[0] = t; }
    __syncthreads();
    float inv = 1.f / red[0];
    __syncthreads();

    int gi = tid >> 6, d = tid & 63;
    float acc = 0.f;
    for (int j = gi; j < NTOK; j += 4)
        acc += sl[j] * qkv[(size_t)j * QKVW + 1024 + h * DH + d];
    part[gi][d] = acc;
    __syncthreads();
    if (tid < DH)
        attn[h * DH + tid] = (part[0][tid] + part[1][tid] + part[2][tid] + part[3][tid]) * inv;
}

// ---------------------------------------------------------------- time attention
__global__ void time_attn_kernel(const float* __restrict__ qkv, float* __restrict__ attn)
{
    int w = (blockIdx.x * blockDim.x + threadIdx.x) >> 5;
    int lane = threadIdx.x & 31;
    if (w >= NHEAD * NSP * FRAMES) return;
    int h = w / (NSP * FRAMES);
    int rem = w % (NSP * FRAMES);
    int nn = rem / FRAMES;
    int f  = rem % FRAMES;
    int qt = 1 + f * NSP + nn;

    const float* qb = qkv + (size_t)qt * QKVW + h * DH;
    float q0 = ASCALE * qb[lane], q1 = ASCALE * qb[lane + 32];

    int kt[5] = {0, 1 + nn, 1 + NSP + nn, 1 + 2 * NSP + nn, 1 + 3 * NSP + nn};
    float lg[5];
#pragma unroll
    for (int j = 0; j < 5; j++) {
        const float* kb = qkv + (size_t)kt[j] * QKVW + 512 + h * DH;
        float p = q0 * kb[lane] + q1 * kb[lane + 32];
#pragma unroll
        for (int o = 16; o; o >>= 1) p += __shfl_xor_sync(0xffffffffu, p, o);
        lg[j] = p;
    }
    float m = lg[0];
#pragma unroll
    for (int j = 1; j < 5; j++) m = fmaxf(m, lg[j]);
    float e[5], s = 0.f;
#pragma unroll
    for (int j = 0; j < 5; j++) { e[j] = expf(lg[j] - m); s += e[j]; }
    float inv = 1.f / s;

    float o0 = 0.f, o1 = 0.f;
#pragma unroll
    for (int j = 0; j < 5; j++) {
        const float* vb = qkv + (size_t)kt[j] * QKVW + 1024 + h * DH;
        float p = e[j] * inv;
        o0 += p * vb[lane];
        o1 += p * vb[lane + 32];
    }
    attn[(size_t)qt * D + h * DH + lane]      = o0;
    attn[(size_t)qt * D + h * DH + lane + 32] = o1;
}

// ---------------------------------------------------------------- space attention: scores
__global__ void space_scores_kernel(const float* __restrict__ qkv, float* __restrict__ S)
{
    int g = blockIdx.z;
    int h = g >> 3, f = (g >> 1) & 3, half = g & 1;
    int i0 = blockIdx.x * 64;
    int j0 = blockIdx.y * 64;
    int tid = threadIdx.x;
    int tx = tid & 15, ty = tid >> 4;

    __shared__ float Qs[64][65];
    __shared__ float Ks[64][65];

#pragma unroll
    for (int u = 0; u < 16; u++) {
        int idx = tid + u * 256;
        int r = idx >> 6, d = idx & 63;
        int i = i0 + r;
        float v = 0.f;
        if (i < HALFN) {
            int qt = 1 + f * NSP + half * HALFN + i;
            v = ASCALE * qkv[(size_t)qt * QKVW + h * DH + d];
        }
        Qs[r][d] = v;
    }
#pragma unroll
    for (int u = 0; u < 16; u++) {
        int idx = tid + u * 256;
        int r = idx >> 6, d = idx & 63;
        int j = j0 + r;
        float v = 0.f;
        if (j < NKEY) {
            int kt = (j == 0) ? 0 : 1 + f * NSP + (1 - half) * HALFN + (j - 1);
            v = qkv[(size_t)kt * QKVW + 512 + h * DH + d];
        }
        Ks[r][d] = v;
    }
    __syncthreads();

    float acc[4][4];
#pragma unroll
    for (int a = 0; a < 4; a++)
#pragma unroll
        for (int b = 0; b < 4; b++) acc[a][b] = 0.f;

#pragma unroll
    for (int k = 0; k < 64; k++) {
        float ra[4], rb[4];
#pragma unroll
        for (int a = 0; a < 4; a++) ra[a] = Qs[ty * 4 + a][k];
#pragma unroll
        for (int b = 0; b < 4; b++) rb[b] = Ks[tx * 4 + b][k];
#pragma unroll
        for (int a = 0; a < 4; a++)
#pragma unroll
            for (int b = 0; b < 4; b++) acc[a][b] += ra[a] * rb[b];
    }

#pragma unroll
    for (int a = 0; a < 4; a++) {
        int i = i0 + ty * 4 + a;
        if (i >= HALFN) continue;
#pragma unroll
        for (int b = 0; b < 4; b++) {
            int j = j0 + tx * 4 + b;
            if (j >= NKEY) continue;
            S[(size_t)g * HALFN * NKEY + (size_t)i * NKEY + j] = acc[a][b];
        }
    }
}

// ---------------------------------------------------------------- softmax rows
__global__ void softmax_kernel(float* __restrict__ S)
{
    int row = blockIdx.x;
    float* r = S + (size_t)row * NKEY;
    int tid = threadIdx.x;  // 128
    __shared__ float red[4];

    float m = -1e30f;
    for (int j = tid; j < NKEY; j += 128) m = fmaxf(m, r[j]);
#pragma unroll
    for (int o = 16; o; o >>= 1) m = fmaxf(m, __shfl_xor_sync(0xffffffffu, m, o));
    if ((tid & 31) == 0) red[tid >> 5] = m;
    __syncthreads();
    if (tid == 0) { float t = red[0]; for (int i = 1; i < 4; i++) t = fmaxf(t, red[i]); red[0] = t; }
    __syncthreads();
    m = red[0];
    __syncthreads();

    float s = 0.f;
    for (int j = tid; j < NKEY; j += 128) {
        float e = expf(r[j] - m);
        r[j] = e;
        s += e;
    }
#pragma unroll
    for (int o = 16; o; o >>= 1) s += __shfl_xor_sync(0xffffffffu, s, o);
    if ((tid & 31) == 0) red[tid >> 5] = s;
    __syncthreads();
    if (tid == 0) { float t = 0; for (int i = 0; i < 4; i++) t += red[i]; red[0] = t; }
    __syncthreads();
    float inv = 1.f / red[0];
    for (int j = tid; j < NKEY; j += 128) r[j] *= inv;
}

// ---------------------------------------------------------------- space attention: P @ V
__global__ void space_av_kernel(const float* __restrict__ S, const float* __restrict__ qkv,
                                float* __restrict__ attn)
{
    int g = blockIdx.z;
    int h = g >> 3, f = (g >> 1) & 3, half = g & 1;
    int i0 = blockIdx.x * 64;
    int tid = threadIdx.x;
    int tx = tid & 15, ty = tid >> 4;

    __shared__ float Ps[64][65];
    __shared__ float Vs[64][65];

    float acc[4][4];
#pragma unroll
    for (int a = 0; a < 4; a++)
#pragma unroll
        for (int b = 0; b < 4; b++) acc[a][b] = 0.f;

    const float* Srow = S + (size_t)g * HALFN * NKEY;

    for (int j0 = 0; j0 < NKEY; j0 += 64) {
#pragma unroll
        for (int u = 0; u < 16; u++) {
            int idx = tid + u * 256;
            int rr = idx >> 6, cc = idx & 63;
            int i = i0 + rr, j = j0 + cc;
            Ps[rr][cc] = (i < HALFN && j < NKEY) ? Srow[(size_t)i * NKEY + j] : 0.f;
        }
#pragma unroll
        for (int u = 0; u < 16; u++) {
            int idx = tid + u * 256;
            int rr = idx >> 6, dd = idx & 63;
            int j = j0 + rr;
            float v = 0.f;
            if (j < NKEY) {
                int kt = (j == 0) ? 0 : 1 + f * NSP + (1 - half) * HALFN + (j - 1);
                v = qkv[(size_t)kt * QKVW + 1024 + h * DH + dd];
            }
            Vs[rr][dd] = v;
        }
        __syncthreads();
#pragma unroll
        for (int k = 0; k < 64; k++) {
            float ra[4], rb[4];
#pragma unroll
            for (int a = 0; a < 4; a++) ra[a] = Ps[ty * 4 + a][k];
#pragma unroll
            for (int b = 0; b < 4; b++) rb[b] = Vs[k][tx * 4 + b];
#pragma unroll
            for (int a = 0; a < 4; a++)
#pragma unroll
                for (int b = 0; b < 4; b++) acc[a][b] += ra[a] * rb[b];
        }
        __syncthreads();
    }

#pragma unroll
    for (int a = 0; a < 4; a++) {
        int i = i0 + ty * 4 + a;
        if (i >= HALFN) continue;
        int qt = 1 + f * NSP + half * HALFN + i;
#pragma unroll
        for (int b = 0; b < 4; b++)
            attn[(size_t)qt * D + h * DH + tx * 4 + b] = acc[a][b];
    }
}

// ---------------------------------------------------------------- GEGLU
__global__ void geglu_kernel(const float* __restrict__ h, float* __restrict__ act)
{
    int idx = blockIdx.x * blockDim.x + threadIdx.x;
    if (idx >= NTOK * FF2) return;
    int t = idx / FF2, j = idx % FF2;
    float u = h[(size_t)t * FF1 + j];
    float g = h[(size_t)t * FF1 + FF2 + j];
    float ge = 0.5f * g * (1.f + erff(g * 0.70710678118654752f));
    act[idx] = u * ge;
}

// ---------------------------------------------------------------- head
__global__ void head_kernel(const float* __restrict__ xn, const float* __restrict__ ow,
                            const float* __restrict__ ob, float* __restrict__ out)
{
    int tid = threadIdx.x;
    if (tid >= 60) return;
    float s = ob[tid];
    for (int d = 0; d < D; d++) s += xn[d] * ow[d * 60 + tid];
    out[tid] = s;
}

}  // namespace

extern "C" void kernel_launch(void* const* d_in, const int* in_sizes, int n_in,
                              void* d_out, int out_size)
{
    const float* video   = (const float*)d_in[0];
    const float* patch_w = (const float*)d_in[1];
    const float* patch_b = (const float*)d_in[2];
    const float* pos_emb = (const float*)d_in[3];
    const float* cls_tok = (const float*)d_in[4];
    const float* t_ln_g  = (const float*)d_in[5];
    const float* t_ln_b  = (const float*)d_in[6];
    const float* t_qkv_w = (const float*)d_in[7];
    const float* t_out_w = (const float*)d_in[8];
    const float* t_out_b = (const float*)d_in[9];
    const float* s_ln_g  = (const float*)d_in[10];
    const float* s_ln_b  = (const float*)d_in[11];
    const float* s_qkv_w = (const float*)d_in[12];
    const float* s_out_w = (const float*)d_in[13];
    const float* s_out_b = (const float*)d_in[14];
    const float* f_ln_g  = (const float*)d_in[15];
    const float* f_ln_b  = (const float*)d_in[16];
    const float* f_w1    = (const float*)d_in[17];
    const float* f_b1    = (const float*)d_in[18];
    const float* f_w2    = (const float*)d_in[19];
    const float* f_b2    = (const float*)d_in[20];
    const float* o_ln_g  = (const float*)d_in[21];
    const float* o_ln_b  = (const float*)d_in[22];
    const float* o_w     = (const float*)d_in[23];
    const float* o_b     = (const float*)d_in[24];
    float* out = (float*)d_out;

    float *x, *xn, *attn, *qkv, *tok, *hbuf, *act, *S;
    cudaGetSymbolAddress((void**)&x,    g_x);
    cudaGetSymbolAddress((void**)&xn,   g_xn);
    cudaGetSymbolAddress((void**)&attn, g_attn);
    cudaGetSymbolAddress((void**)&qkv,  g_qkv);
    cudaGetSymbolAddress((void**)&tok,  g_tok);
    cudaGetSymbolAddress((void**)&hbuf, g_h);
    cudaGetSymbolAddress((void**)&act,  g_act);
    cudaGetSymbolAddress((void**)&S,    g_S);

    auto gemm = [&](const float* A, const float* B, const float* bias, const float* resid,
                    float* C, int M, int N, int K) {
        dim3 grid(N / 128, (M + 127) / 128);
        tgemm_kernel<<<grid, 256>>>(A, B, bias, resid, C, M, N, K);
    };

    // ---- patch embed + pos + cls ----
    patchify_kernel<<<(NPATCH * PD + 255) / 256, 256>>>(video, tok);
    gemm(tok, patch_w, patch_b, nullptr, x + D, NPATCH, D, PD);
    addpos_kernel<<<(NTOK * D + 255) / 256, 256>>>(x, cls_tok, pos_emb);

    for (int i = 0; i < 12; i++) {
        // ---------------- time attention ----------------
        layernorm_kernel<<<NTOK, 256>>>(x, t_ln_g + i * D, t_ln_b + i * D, xn, NTOK);
        gemm(xn, t_qkv_w + (size_t)i * D * QKVW, nullptr, nullptr, qkv, NTOK, QKVW, D);
        cls_attn_kernel<<<NHEAD, 256>>>(qkv, attn);
        time_attn_kernel<<<(NHEAD * NSP * FRAMES * 32 + 255) / 256, 256>>>(qkv, attn);
        gemm(attn, t_out_w + (size_t)i * D * D, t_out_b + i * D, x, x, NTOK, D, D);

        // ---------------- space attention ----------------
        layernorm_kernel<<<NTOK, 256>>>(x, s_ln_g + i * D, s_ln_b + i * D, xn, NTOK);
        gemm(xn, s_qkv_w + (size_t)i * D * QKVW, nullptr, nullptr, qkv, NTOK, QKVW, D);
        cls_attn_kernel<<<NHEAD, 256>>>(qkv, attn);
        {
            dim3 gs((HALFN + 63) / 64, (NKEY + 63) / 64, NGRP);
            space_scores_kernel<<<gs, 256>>>(qkv, S);
            softmax_kernel<<<NGRP * HALFN, 128>>>(S);
            dim3 ga((HALFN + 63) / 64, 1, NGRP);
            space_av_kernel<<<ga, 256>>>(S, qkv, attn);
        }
        gemm(attn, s_out_w + (size_t)i * D * D, s_out_b + i * D, x, x, NTOK, D, D);

        // ---------------- GEGLU FF ----------------
        layernorm_kernel<<<NTOK, 256>>>(x, f_ln_g + i * D, f_ln_b + i * D, xn, NTOK);
        gemm(xn, f_w1 + (size_t)i * D * FF1, f_b1 + i * FF1, nullptr, hbuf, NTOK, FF1, D);
        geglu_kernel<<<(NTOK * FF2 + 255) / 256, 256>>>(hbuf, act);
        gemm(act, f_w2 + (size_t)i * FF2 * D, f_b2 + i * D, x, x, NTOK, D, FF2);
    }

    // ---- final LN on cls + head ----
    layernorm_kernel<<<1, 256>>>(x, o_ln_g, o_ln_b, xn, 1);
    head_kernel<<<1, 64>>>(xn, o_w, o_b, out);
}

// round 5
// speedup vs baseline: 1.8906x; 1.0733x over previous
#include <cuda_runtime.h>
#include <cuda_bf16.h>
#include <math.h>

namespace {

typedef unsigned int uint;

constexpr int NTOK  = 4801;
constexpr int D     = 512;
constexpr int QKVW  = 1536;
constexpr int FRAMES= 4;
constexpr int NSP   = 1200;
constexpr int HALFN = 600;
constexpr int NKEY  = 601;
constexpr int NHEAD = 8;
constexpr int DH    = 64;
constexpr float ASCALE = 0.125f;
constexpr int FF1   = 4096;
constexpr int FF2   = 2048;
constexpr int NPATCH= 4800;
constexpr int PD    = 768;
constexpr int NGRP  = 64;

// fp32 buffers
__device__ float g_x   [NTOK * D];
__device__ float g_xn  [D];                 // final LN only
__device__ float g_qkv [NTOK * QKVW];
__device__ float g_h   [NTOK * FF1];
__device__ float g_S   [(size_t)NGRP * HALFN * NKEY];

// packed bf16x2 hi/lo activation buffers (pair index = k/2)
__device__ uint g_xnH [NTOK * 256],  g_xnL [NTOK * 256];
__device__ uint g_atH [NTOK * 256],  g_atL [NTOK * 256];
__device__ uint g_acH [NTOK * 1024], g_acL [NTOK * 1024];
__device__ uint g_tkH [NPATCH * 384], g_tkL [NPATCH * 384];

// packed split weights (all 12 layers)
__device__ uint g_wqtH[12 * 256 * QKVW], g_wqtL[12 * 256 * QKVW];
__device__ uint g_wqsH[12 * 256 * QKVW], g_wqsL[12 * 256 * QKVW];
__device__ uint g_wotH[12 * 256 * D],    g_wotL[12 * 256 * D];
__device__ uint g_wosH[12 * 256 * D],    g_wosL[12 * 256 * D];
__device__ uint g_w1H [12 * 256 * FF1],  g_w1L [12 * 256 * FF1];
__device__ uint g_w2H [12 * 1024 * D],   g_w2L [12 * 1024 * D];
__device__ uint g_wpH [384 * D],         g_wpL [384 * D];

__device__ __forceinline__ void split2(float x0, float x1, uint& hi, uint& lo) {
    __nv_bfloat16 h0 = __float2bfloat16(x0);
    __nv_bfloat16 h1 = __float2bfloat16(x1);
    __nv_bfloat16 l0 = __float2bfloat16(x0 - __bfloat162float(h0));
    __nv_bfloat16 l1 = __float2bfloat16(x1 - __bfloat162float(h1));
    __nv_bfloat162 H = __nv_bfloat162(h0, h1);
    __nv_bfloat162 L = __nv_bfloat162(l0, l1);
    hi = *reinterpret_cast<uint*>(&H);
    lo = *reinterpret_cast<uint*>(&L);
}

__device__ __forceinline__ void mma_bf16(float* acc, const uint* a, const uint* b) {
    asm volatile(
        "mma.sync.aligned.m16n8k16.row.col.f32.bf16.bf16.f32 "
        "{%0,%1,%2,%3}, {%4,%5,%6,%7}, {%8,%9}, {%0,%1,%2,%3};"
        : "+f"(acc[0]), "+f"(acc[1]), "+f"(acc[2]), "+f"(acc[3])
        : "r"(a[0]), "r"(a[1]), "r"(a[2]), "r"(a[3]), "r"(b[0]), "r"(b[1]));
}

// ---------------------------------------------------------------- weight split prep
// W:[2*Kp][N] fp32 -> H/L:[Kp][N] packed bf16x2 (pair along k)
__global__ void split_w_kernel(const float* __restrict__ W, uint* __restrict__ H,
                               uint* __restrict__ L, int N, long long total)
{
    long long idx = (long long)blockIdx.x * blockDim.x + threadIdx.x;
    if (idx >= total) return;
    long long kp = idx / N;
    int n = (int)(idx - kp * N);
    float x0 = W[(size_t)(2 * kp) * N + n];
    float x1 = W[(size_t)(2 * kp + 1) * N + n];
    split2(x0, x1, H[idx], L[idx]);
}

// ---------------------------------------------------------------- split-bf16 GEMM (pre-split operands)
// C[M,2*Kp?] no: C[M,N] = A[M,K] @ B[K,N], K = 2*Kp. A as (AH,AL)[M][Kp], B as (BH,BL)[Kp][N].
// BM=128 BN=128 BKp=16 (K=32). 256 thr, 8 warps, warp tile 64x32, 3-term hi/lo.
__global__ __launch_bounds__(256)
void bgemm_kernel(const uint* __restrict__ AH, const uint* __restrict__ AL,
                  const uint* __restrict__ BH, const uint* __restrict__ BL,
                  const float* __restrict__ bias, const float* __restrict__ resid,
                  float* __restrict__ C, int M, int N, int Kp)
{
    __shared__ uint AsH[128][20], AsL[128][20];
    __shared__ uint BsH[16][136], BsL[16][136];

    const int tid  = threadIdx.x;
    const int lane = tid & 31;
    const int warp = tid >> 5;
    const int grp  = lane >> 2;
    const int qid  = lane & 3;
    const int wm   = (warp & 1) * 64;
    const int wn   = (warp >> 1) * 32;
    const int row0 = blockIdx.y * 128;
    const int col0 = blockIdx.x * 128;

    float acc[4][4][4];
#pragma unroll
    for (int mt = 0; mt < 4; mt++)
#pragma unroll
        for (int nt = 0; nt < 4; nt++)
#pragma unroll
            for (int e = 0; e < 4; e++) acc[mt][nt][e] = 0.f;

    uint4 aH[2], aL[2], bH[2], bL[2];

    auto gload = [&](int kp0) {
#pragma unroll
        for (int u = 0; u < 2; u++) {
            int idx = tid + u * 256;           // 0..511
            int r = idx >> 2, c4 = idx & 3;    // row, uint4-col (4 per row of 16 pairs)
            int gr = row0 + r;
            if (gr < M) {
                aH[u] = *reinterpret_cast<const uint4*>(AH + (size_t)gr * Kp + kp0 + c4 * 4);
                aL[u] = *reinterpret_cast<const uint4*>(AL + (size_t)gr * Kp + kp0 + c4 * 4);
            } else {
                aH[u] = make_uint4(0, 0, 0, 0);
                aL[u] = make_uint4(0, 0, 0, 0);
            }
        }
#pragma unroll
        for (int u = 0; u < 2; u++) {
            int idx = tid + u * 256;
            int kr = idx >> 5, c4 = idx & 31;
            size_t off = (size_t)(kp0 + kr) * N + col0 + c4 * 4;
            bH[u] = *reinterpret_cast<const uint4*>(BH + off);
            bL[u] = *reinterpret_cast<const uint4*>(BL + off);
        }
    };

    auto sstore = [&]() {
#pragma unroll
        for (int u = 0; u < 2; u++) {
            int idx = tid + u * 256;
            int r = idx >> 2, c4 = idx & 3;
            *reinterpret_cast<uint4*>(&AsH[r][c4 * 4]) = aH[u];
            *reinterpret_cast<uint4*>(&AsL[r][c4 * 4]) = aL[u];
        }
#pragma unroll
        for (int u = 0; u < 2; u++) {
            int idx = tid + u * 256;
            int kr = idx >> 5, c4 = idx & 31;
            *reinterpret_cast<uint4*>(&BsH[kr][c4 * 4]) = bH[u];
            *reinterpret_cast<uint4*>(&BsL[kr][c4 * 4]) = bL[u];
        }
    };

    auto compute = [&]() {
#pragma unroll
        for (int kk = 0; kk < 2; kk++) {
            uint bhf[4][2], blf[4][2];
#pragma unroll
            for (int nt = 0; nt < 4; nt++) {
                int c = wn + nt * 8 + grp;
                bhf[nt][0] = BsH[kk * 8 + qid    ][c];
                bhf[nt][1] = BsH[kk * 8 + qid + 4][c];
                blf[nt][0] = BsL[kk * 8 + qid    ][c];
                blf[nt][1] = BsL[kk * 8 + qid + 4][c];
            }
#pragma unroll
            for (int mt = 0; mt < 4; mt++) {
                int r = wm + mt * 16;
                uint ah[4], al[4];
                ah[0] = AsH[r + grp    ][kk * 8 + qid    ];
                ah[1] = AsH[r + grp + 8][kk * 8 + qid    ];
                ah[2] = AsH[r + grp    ][kk * 8 + qid + 4];
                ah[3] = AsH[r + grp + 8][kk * 8 + qid + 4];
                al[0] = AsL[r + grp    ][kk * 8 + qid    ];
                al[1] = AsL[r + grp + 8][kk * 8 + qid    ];
                al[2] = AsL[r + grp    ][kk * 8 + qid + 4];
                al[3] = AsL[r + grp + 8][kk * 8 + qid + 4];
#pragma unroll
                for (int nt = 0; nt < 4; nt++) {
                    mma_bf16(acc[mt][nt], al, bhf[nt]);   // lo*hi
                    mma_bf16(acc[mt][nt], ah, blf[nt]);   // hi*lo
                    mma_bf16(acc[mt][nt], ah, bhf[nt]);   // hi*hi
                }
            }
        }
    };

    gload(0);
    sstore();
    __syncthreads();
    for (int kp0 = 16; kp0 < Kp; kp0 += 16) {
        gload(kp0);
        compute();
        __syncthreads();
        sstore();
        __syncthreads();
    }
    compute();

#pragma unroll
    for (int mt = 0; mt < 4; mt++) {
#pragma unroll
        for (int e2 = 0; e2 < 2; e2++) {
            int gr = row0 + wm + mt * 16 + grp + e2 * 8;
            if (gr >= M) continue;
#pragma unroll
            for (int nt = 0; nt < 4; nt++) {
                int gc = col0 + wn + nt * 8 + qid * 2;
                float v0 = acc[mt][nt][e2 * 2 + 0];
                float v1 = acc[mt][nt][e2 * 2 + 1];
                if (bias)  { v0 += bias[gc]; v1 += bias[gc + 1]; }
                if (resid) {
                    v0 += resid[(size_t)gr * N + gc];
                    v1 += resid[(size_t)gr * N + gc + 1];
                }
                C[(size_t)gr * N + gc]     = v0;
                C[(size_t)gr * N + gc + 1] = v1;
            }
        }
    }
}

// ---------------------------------------------------------------- patchify (packed split out)
__global__ void patchify_kernel(const float* __restrict__ video,
                                uint* __restrict__ tH, uint* __restrict__ tL)
{
    int idx = blockIdx.x * blockDim.x + threadIdx.x;
    if (idx >= NPATCH * 384) return;
    int t = idx / 384, pp = idx % 384;
    int side = t / 2400;
    int r = t % 2400;
    int f = r / 600;
    int rr = r % 600;
    int ph = rr / 20;
    int pw = rr % 20;
    float v[2];
#pragma unroll
    for (int e = 0; e < 2; e++) {
        int pd = pp * 2 + e;
        int p1 = pd / 48;
        int rem = pd % 48;
        int p2 = rem / 3;
        int c  = rem % 3;
        int row = ph * 16 + p1;
        int col = side * 320 + pw * 16 + p2;
        v[e] = video[(((size_t)f * 3 + c) * 480 + row) * 640 + col];
    }
    split2(v[0], v[1], tH[idx], tL[idx]);
}

__global__ void addpos_kernel(float* __restrict__ x, const float* __restrict__ cls,
                              const float* __restrict__ pos)
{
    int idx = blockIdx.x * blockDim.x + threadIdx.x;
    if (idx >= NTOK * D) return;
    if (idx < D) x[idx] = cls[idx] + pos[idx];
    else         x[idx] += pos[idx];
}

// ---------------------------------------------------------------- LayerNorm (packed split out)
__global__ void layernorm_pack_kernel(const float* __restrict__ x, const float* __restrict__ g,
                                      const float* __restrict__ b,
                                      uint* __restrict__ oH, uint* __restrict__ oL)
{
    int row = blockIdx.x;
    int tid = threadIdx.x;  // 256, each handles dims 2t, 2t+1
    const float* xr = x + (size_t)row * D;
    float2 xv = *reinterpret_cast<const float2*>(xr + 2 * tid);
    __shared__ float red[8];

    float s = xv.x + xv.y;
#pragma unroll
    for (int o = 16; o; o >>= 1) s += __shfl_xor_sync(0xffffffffu, s, o);
    if ((tid & 31) == 0) red[tid >> 5] = s;
    __syncthreads();
    if (tid == 0) { float t = 0; for (int i = 0; i < 8; i++) t += red[i]; red[0] = t; }
    __syncthreads();
    float mu = red[0] * (1.f / 512.f);
    __syncthreads();

    float d0 = xv.x - mu, d1 = xv.y - mu;
    float v = d0 * d0 + d1 * d1;
#pragma unroll
    for (int o = 16; o; o >>= 1) v += __shfl_xor_sync(0xffffffffu, v, o);
    if ((tid & 31) == 0) red[tid >> 5] = v;
    __syncthreads();
    if (tid == 0) { float t = 0; for (int i = 0; i < 8; i++) t += red[i]; red[0] = t; }
    __syncthreads();
    float rstd = rsqrtf(red[0] * (1.f / 512.f) + 1e-5f);

    float2 gv = *reinterpret_cast<const float2*>(g + 2 * tid);
    float2 bv = *reinterpret_cast<const float2*>(b + 2 * tid);
    split2(d0 * rstd * gv.x + bv.x, d1 * rstd * gv.y + bv.y,
           oH[(size_t)row * 256 + tid], oL[(size_t)row * 256 + tid]);
}

// ---------------------------------------------------------------- final LayerNorm (fp32, row 0)
__global__ void layernorm_kernel(const float* __restrict__ x, const float* __restrict__ g,
                                 const float* __restrict__ b, float* __restrict__ out)
{
    int tid = threadIdx.x;  // 256
    float x0 = x[tid], x1 = x[tid + 256];
    __shared__ float red[8];

    float s = x0 + x1;
#pragma unroll
    for (int o = 16; o; o >>= 1) s += __shfl_xor_sync(0xffffffffu, s, o);
    if ((tid & 31) == 0) red[tid >> 5] = s;
    __syncthreads();
    if (tid == 0) { float t = 0; for (int i = 0; i < 8; i++) t += red[i]; red[0] = t; }
    __syncthreads();
    float mu = red[0] * (1.f / 512.f);
    __syncthreads();

    float d0 = x0 - mu, d1 = x1 - mu;
    float v = d0 * d0 + d1 * d1;
#pragma unroll
    for (int o = 16; o; o >>= 1) v += __shfl_xor_sync(0xffffffffu, v, o);
    if ((tid & 31) == 0) red[tid >> 5] = v;
    __syncthreads();
    if (tid == 0) { float t = 0; for (int i = 0; i < 8; i++) t += red[i]; red[0] = t; }
    __syncthreads();
    float rstd = rsqrtf(red[0] * (1.f / 512.f) + 1e-5f);

    out[tid]       = d0 * rstd * g[tid] + b[tid];
    out[tid + 256] = d1 * rstd * g[tid + 256] + b[tid + 256];
}

// ---------------------------------------------------------------- cls attention (packed out)
__global__ void cls_attn_kernel(const float* __restrict__ qkv,
                                uint* __restrict__ aH, uint* __restrict__ aL)
{
    int h = blockIdx.x;
    int tid = threadIdx.x;  // 256
    __shared__ float sl[NTOK];
    __shared__ float qs[DH];
    __shared__ float red[8];
    __shared__ float part[4][DH];

    if (tid < DH) qs[tid] = ASCALE * qkv[h * DH + tid];
    __syncthreads();

    float lmax = -1e30f;
    for (int j = tid; j < NTOK; j += 256) {
        const float* kb = qkv + (size_t)j * QKVW + 512 + h * DH;
        float s = 0.f;
#pragma unroll
        for (int d = 0; d < DH; d++) s += qs[d] * kb[d];
        sl[j] = s;
        lmax = fmaxf(lmax, s);
    }
#pragma unroll
    for (int o = 16; o; o >>= 1) lmax = fmaxf(lmax, __shfl_xor_sync(0xffffffffu, lmax, o));
    if ((tid & 31) == 0) red[tid >> 5] = lmax;
    __syncthreads();
    if (tid == 0) { float m = red[0]; for (int i = 1; i < 8; i++) m = fmaxf(m, red[i]); red[0] = m; }
    __syncthreads();
    float mx = red[0];
    __syncthreads();

    float lsum = 0.f;
    for (int j = tid; j < NTOK; j += 256) {
        float e = expf(sl[j] - mx);
        sl[j] = e;
        lsum += e;
    }
#pragma unroll
    for (int o = 16; o; o >>= 1) lsum += __shfl_xor_sync(0xffffffffu, lsum, o);
    if ((tid & 31) == 0) red[tid >> 5] = lsum;
    __syncthreads();
    if (tid == 0) { float t = 0; for (int i = 0; i < 8; i++) t += red[i]; red[0] = t; }
    __syncthreads();
    float inv = 1.f / red[0];
    __syncthreads();

    int gi = tid >> 6, d = tid & 63;
    float acc = 0.f;
    for (int j = gi; j < NTOK; j += 4)
        acc += sl[j] * qkv[(size_t)j * QKVW + 1024 + h * DH + d];
    part[gi][d] = acc;
    __syncthreads();
    if (tid < 32) {
        float v0 = (part[0][2*tid]   + part[1][2*tid]   + part[2][2*tid]   + part[3][2*tid])   * inv;
        float v1 = (part[0][2*tid+1] + part[1][2*tid+1] + part[2][2*tid+1] + part[3][2*tid+1]) * inv;
        split2(v0, v1, aH[h * 32 + tid], aL[h * 32 + tid]);   // row 0
    }
}

// ---------------------------------------------------------------- time attention (packed out)
__global__ void time_attn_kernel(const float* __restrict__ qkv,
                                 uint* __restrict__ aH, uint* __restrict__ aL)
{
    int w = (blockIdx.x * blockDim.x + threadIdx.x) >> 5;
    int lane = threadIdx.x & 31;
    if (w >= NHEAD * NSP * FRAMES) return;
    int h = w / (NSP * FRAMES);
    int rem = w % (NSP * FRAMES);
    int nn = rem / FRAMES;
    int f  = rem % FRAMES;
    int qt = 1 + f * NSP + nn;

    const float* qb = qkv + (size_t)qt * QKVW + h * DH;
    float q0 = ASCALE * qb[2 * lane], q1 = ASCALE * qb[2 * lane + 1];

    int kt[5] = {0, 1 + nn, 1 + NSP + nn, 1 + 2 * NSP + nn, 1 + 3 * NSP + nn};
    float lg[5];
#pragma unroll
    for (int j = 0; j < 5; j++) {
        const float* kb = qkv + (size_t)kt[j] * QKVW + 512 + h * DH;
        float p = q0 * kb[2 * lane] + q1 * kb[2 * lane + 1];
#pragma unroll
        for (int o = 16; o; o >>= 1) p += __shfl_xor_sync(0xffffffffu, p, o);
        lg[j] = p;
    }
    float m = lg[0];
#pragma unroll
    for (int j = 1; j < 5; j++) m = fmaxf(m, lg[j]);
    float e[5], s = 0.f;
#pragma unroll
    for (int j = 0; j < 5; j++) { e[j] = expf(lg[j] - m); s += e[j]; }
    float inv = 1.f / s;

    float o0 = 0.f, o1 = 0.f;
#pragma unroll
    for (int j = 0; j < 5; j++) {
        const float* vb = qkv + (size_t)kt[j] * QKVW + 1024 + h * DH;
        float p = e[j] * inv;
        o0 += p * vb[2 * lane];
        o1 += p * vb[2 * lane + 1];
    }
    split2(o0, o1, aH[(size_t)qt * 256 + h * 32 + lane], aL[(size_t)qt * 256 + h * 32 + lane]);
}

// ---------------------------------------------------------------- space attention: scores
__global__ void space_scores_kernel(const float* __restrict__ qkv, float* __restrict__ S)
{
    int g = blockIdx.z;
    int h = g >> 3, f = (g >> 1) & 3, half = g & 1;
    int i0 = blockIdx.x * 64;
    int j0 = blockIdx.y * 64;
    int tid = threadIdx.x;
    int tx = tid & 15, ty = tid >> 4;

    __shared__ float Qs[64][65];
    __shared__ float Ks[64][65];

#pragma unroll
    for (int u = 0; u < 16; u++) {
        int idx = tid + u * 256;
        int r = idx >> 6, d = idx & 63;
        int i = i0 + r;
        float v = 0.f;
        if (i < HALFN) {
            int qt = 1 + f * NSP + half * HALFN + i;
            v = ASCALE * qkv[(size_t)qt * QKVW + h * DH + d];
        }
        Qs[r][d] = v;
    }
#pragma unroll
    for (int u = 0; u < 16; u++) {
        int idx = tid + u * 256;
        int r = idx >> 6, d = idx & 63;
        int j = j0 + r;
        float v = 0.f;
        if (j < NKEY) {
            int kt = (j == 0) ? 0 : 1 + f * NSP + (1 - half) * HALFN + (j - 1);
            v = qkv[(size_t)kt * QKVW + 512 + h * DH + d];
        }
        Ks[r][d] = v;
    }
    __syncthreads();

    float acc[4][4];
#pragma unroll
    for (int a = 0; a < 4; a++)
#pragma unroll
        for (int b = 0; b < 4; b++) acc[a][b] = 0.f;

#pragma unroll
    for (int k = 0; k < 64; k++) {
        float ra[4], rb[4];
#pragma unroll
        for (int a = 0; a < 4; a++) ra[a] = Qs[ty * 4 + a][k];
#pragma unroll
        for (int b = 0; b < 4; b++) rb[b] = Ks[tx * 4 + b][k];
#pragma unroll
        for (int a = 0; a < 4; a++)
#pragma unroll
            for (int b = 0; b < 4; b++) acc[a][b] += ra[a] * rb[b];
    }

#pragma unroll
    for (int a = 0; a < 4; a++) {
        int i = i0 + ty * 4 + a;
        if (i >= HALFN) continue;
#pragma unroll
        for (int b = 0; b < 4; b++) {
            int j = j0 + tx * 4 + b;
            if (j >= NKEY) continue;
            S[(size_t)g * HALFN * NKEY + (size_t)i * NKEY + j] = acc[a][b];
        }
    }
}

// ---------------------------------------------------------------- softmax rows
__global__ void softmax_kernel(float* __restrict__ S)
{
    int row = blockIdx.x;
    float* r = S + (size_t)row * NKEY;
    int tid = threadIdx.x;  // 128
    __shared__ float red[4];

    float m = -1e30f;
    for (int j = tid; j < NKEY; j += 128) m = fmaxf(m, r[j]);
#pragma unroll
    for (int o = 16; o; o >>= 1) m = fmaxf(m, __shfl_xor_sync(0xffffffffu, m, o));
    if ((tid & 31) == 0) red[tid >> 5] = m;
    __syncthreads();
    if (tid == 0) { float t = red[0]; for (int i = 1; i < 4; i++) t = fmaxf(t, red[i]); red[0] = t; }
    __syncthreads();
    m = red[0];
    __syncthreads();

    float s = 0.f;
    for (int j = tid; j < NKEY; j += 128) {
        float e = expf(r[j] - m);
        r[j] = e;
        s += e;
    }
#pragma unroll
    for (int o = 16; o; o >>= 1) s += __shfl_xor_sync(0xffffffffu, s, o);
    if ((tid & 31) == 0) red[tid >> 5] = s;
    __syncthreads();
    if (tid == 0) { float t = 0; for (int i = 0; i < 4; i++) t += red[i]; red[0] = t; }
    __syncthreads();
    float inv = 1.f / red[0];
    for (int j = tid; j < NKEY; j += 128) r[j] *= inv;
}

// ---------------------------------------------------------------- space attention: P @ V (packed out)
__global__ void space_av_kernel(const float* __restrict__ S, const float* __restrict__ qkv,
                                uint* __restrict__ aH, uint* __restrict__ aL)
{
    int g = blockIdx.z;
    int h = g >> 3, f = (g >> 1) & 3, half = g & 1;
    int i0 = blockIdx.x * 64;
    int tid = threadIdx.x;
    int tx = tid & 15, ty = tid >> 4;

    __shared__ float Ps[64][65];
    __shared__ float Vs[64][65];

    float acc[4][4];
#pragma unroll
    for (int a = 0; a < 4; a++)
#pragma unroll
        for (int b = 0; b < 4; b++) acc[a][b] = 0.f;

    const float* Srow = S + (size_t)g * HALFN * NKEY;

    for (int j0 = 0; j0 < NKEY; j0 += 64) {
#pragma unroll
        for (int u = 0; u < 16; u++) {
            int idx = tid + u * 256;
            int rr = idx >> 6, cc = idx & 63;
            int i = i0 + rr, j = j0 + cc;
            Ps[rr][cc] = (i < HALFN && j < NKEY) ? Srow[(size_t)i * NKEY + j] : 0.f;
        }
#pragma unroll
        for (int u = 0; u < 16; u++) {
            int idx = tid + u * 256;
            int rr = idx >> 6, dd = idx & 63;
            int j = j0 + rr;
            float v = 0.f;
            if (j < NKEY) {
                int kt = (j == 0) ? 0 : 1 + f * NSP + (1 - half) * HALFN + (j - 1);
                v = qkv[(size_t)kt * QKVW + 1024 + h * DH + dd];
            }
            Vs[rr][dd] = v;
        }
        __syncthreads();
#pragma unroll
        for (int k = 0; k < 64; k++) {
            float ra[4], rb[4];
#pragma unroll
            for (int a = 0; a < 4; a++) ra[a] = Ps[ty * 4 + a][k];
#pragma unroll
            for (int b = 0; b < 4; b++) rb[b] = Vs[k][tx * 4 + b];
#pragma unroll
            for (int a = 0; a < 4; a++)
#pragma unroll
                for (int b = 0; b < 4; b++) acc[a][b] += ra[a] * rb[b];
        }
        __syncthreads();
    }

#pragma unroll
    for (int a = 0; a < 4; a++) {
        int i = i0 + ty * 4 + a;
        if (i >= HALFN) continue;
        int qt = 1 + f * NSP + half * HALFN + i;
        int base = (size_t)0 + h * 32 + tx * 2;
        split2(acc[a][0], acc[a][1], aH[(size_t)qt * 256 + base],     aL[(size_t)qt * 256 + base]);
        split2(acc[a][2], acc[a][3], aH[(size_t)qt * 256 + base + 1], aL[(size_t)qt * 256 + base + 1]);
    }
}

// ---------------------------------------------------------------- GEGLU (packed out)
__global__ void geglu_kernel(const float* __restrict__ h,
                             uint* __restrict__ oH, uint* __restrict__ oL)
{
    int idx = blockIdx.x * blockDim.x + threadIdx.x;
    if (idx >= NTOK * 1024) return;
    int t = idx / 1024, i = idx % 1024;
    const float* hr = h + (size_t)t * FF1;
    float2 uv = *reinterpret_cast<const float2*>(hr + 2 * i);
    float2 gv = *reinterpret_cast<const float2*>(hr + FF2 + 2 * i);
    float ge0 = 0.5f * gv.x * (1.f + erff(gv.x * 0.70710678118654752f));
    float ge1 = 0.5f * gv.y * (1.f + erff(gv.y * 0.70710678118654752f));
    split2(uv.x * ge0, uv.y * ge1, oH[idx], oL[idx]);
}

// ---------------------------------------------------------------- head
__global__ void head_kernel(const float* __restrict__ xn, const float* __restrict__ ow,
                            const float* __restrict__ ob, float* __restrict__ out)
{
    int tid = threadIdx.x;
    if (tid >= 60) return;
    float s = ob[tid];
    for (int d = 0; d < D; d++) s += xn[d] * ow[d * 60 + tid];
    out[tid] = s;
}

}  // namespace

extern "C" void kernel_launch(void* const* d_in, const int* in_sizes, int n_in,
                              void* d_out, int out_size)
{
    const float* video   = (const float*)d_in[0];
    const float* patch_w = (const float*)d_in[1];
    const float* patch_b = (const float*)d_in[2];
    const float* pos_emb = (const float*)d_in[3];
    const float* cls_tok = (const float*)d_in[4];
    const float* t_ln_g  = (const float*)d_in[5];
    const float* t_ln_b  = (const float*)d_in[6];
    const float* t_qkv_w = (const float*)d_in[7];
    const float* t_out_w = (const float*)d_in[8];
    const float* t_out_b = (const float*)d_in[9];
    const float* s_ln_g  = (const float*)d_in[10];
    const float* s_ln_b  = (const float*)d_in[11];
    const float* s_qkv_w = (const float*)d_in[12];
    const float* s_out_w = (const float*)d_in[13];
    const float* s_out_b = (const float*)d_in[14];
    const float* f_ln_g  = (const float*)d_in[15];
    const float* f_ln_b  = (const float*)d_in[16];
    const float* f_w1    = (const float*)d_in[17];
    const float* f_b1    = (const float*)d_in[18];
    const float* f_w2    = (const float*)d_in[19];
    const float* f_b2    = (const float*)d_in[20];
    const float* o_ln_g  = (const float*)d_in[21];
    const float* o_ln_b  = (const float*)d_in[22];
    const float* o_w     = (const float*)d_in[23];
    const float* o_b     = (const float*)d_in[24];
    float* out = (float*)d_out;

    float *x, *xn, *qkv, *hbuf, *S;
    cudaGetSymbolAddress((void**)&x,    g_x);
    cudaGetSymbolAddress((void**)&xn,   g_xn);
    cudaGetSymbolAddress((void**)&qkv,  g_qkv);
    cudaGetSymbolAddress((void**)&hbuf, g_h);
    cudaGetSymbolAddress((void**)&S,    g_S);

    uint *xnH, *xnL, *atH, *atL, *acH, *acL, *tkH, *tkL;
    cudaGetSymbolAddress((void**)&xnH, g_xnH); cudaGetSymbolAddress((void**)&xnL, g_xnL);
    cudaGetSymbolAddress((void**)&atH, g_atH); cudaGetSymbolAddress((void**)&atL, g_atL);
    cudaGetSymbolAddress((void**)&acH, g_acH); cudaGetSymbolAddress((void**)&acL, g_acL);
    cudaGetSymbolAddress((void**)&tkH, g_tkH); cudaGetSymbolAddress((void**)&tkL, g_tkL);

    uint *wqtH, *wqtL, *wqsH, *wqsL, *wotH, *wotL, *wosH, *wosL, *w1H, *w1L, *w2H, *w2L, *wpH, *wpL;
    cudaGetSymbolAddress((void**)&wqtH, g_wqtH); cudaGetSymbolAddress((void**)&wqtL, g_wqtL);
    cudaGetSymbolAddress((void**)&wqsH, g_wqsH); cudaGetSymbolAddress((void**)&wqsL, g_wqsL);
    cudaGetSymbolAddress((void**)&wotH, g_wotH); cudaGetSymbolAddress((void**)&wotL, g_wotL);
    cudaGetSymbolAddress((void**)&wosH, g_wosH); cudaGetSymbolAddress((void**)&wosL, g_wosL);
    cudaGetSymbolAddress((void**)&w1H,  g_w1H);  cudaGetSymbolAddress((void**)&w1L,  g_w1L);
    cudaGetSymbolAddress((void**)&w2H,  g_w2H);  cudaGetSymbolAddress((void**)&w2L,  g_w2L);
    cudaGetSymbolAddress((void**)&wpH,  g_wpH);  cudaGetSymbolAddress((void**)&wpL,  g_wpL);

    auto splitw = [&](const float* W, uint* H, uint* L, long long Kp_total, int N) {
        long long total = Kp_total * N;
        int blocks = (int)((total + 255) / 256);
        split_w_kernel<<<blocks, 256>>>(W, H, L, N, total);
    };

    // ---- pre-split all weights (flattened over layers; per-layer K is even) ----
    splitw(t_qkv_w, wqtH, wqtL, 12LL * 256, QKVW);
    splitw(s_qkv_w, wqsH, wqsL, 12LL * 256, QKVW);
    splitw(t_out_w, wotH, wotL, 12LL * 256, D);
    splitw(s_out_w, wosH, wosL, 12LL * 256, D);
    splitw(f_w1,    w1H,  w1L,  12LL * 256, FF1);
    splitw(f_w2,    w2H,  w2L,  12LL * 1024, D);
    splitw(patch_w, wpH,  wpL,  384LL, D);

    auto gemm = [&](const uint* AH, const uint* AL, const uint* BH, const uint* BL,
                    const float* bias, const float* resid, float* C, int M, int N, int Kp) {
        dim3 grid(N / 128, (M + 127) / 128);
        bgemm_kernel<<<grid, 256>>>(AH, AL, BH, BL, bias, resid, C, M, N, Kp);
    };

    // ---- patch embed + pos + cls ----
    patchify_kernel<<<(NPATCH * 384 + 255) / 256, 256>>>(video, tkH, tkL);
    gemm(tkH, tkL, wpH, wpL, patch_b, nullptr, x + D, NPATCH, D, 384);
    addpos_kernel<<<(NTOK * D + 255) / 256, 256>>>(x, cls_tok, pos_emb);

    for (int i = 0; i < 12; i++) {
        // ---------------- time attention ----------------
        layernorm_pack_kernel<<<NTOK, 256>>>(x, t_ln_g + i * D, t_ln_b + i * D, xnH, xnL);
        gemm(xnH, xnL, wqtH + (size_t)i * 256 * QKVW, wqtL + (size_t)i * 256 * QKVW,
             nullptr, nullptr, qkv, NTOK, QKVW, 256);
        cls_attn_kernel<<<NHEAD, 256>>>(qkv, atH, atL);
        time_attn_kernel<<<(NHEAD * NSP * FRAMES * 32 + 255) / 256, 256>>>(qkv, atH, atL);
        gemm(atH, atL, wotH + (size_t)i * 256 * D, wotL + (size_t)i * 256 * D,
             t_out_b + i * D, x, x, NTOK, D, 256);

        // ---------------- space attention ----------------
        layernorm_pack_kernel<<<NTOK, 256>>>(x, s_ln_g + i * D, s_ln_b + i * D, xnH, xnL);
        gemm(xnH, xnL, wqsH + (size_t)i * 256 * QKVW, wqsL + (size_t)i * 256 * QKVW,
             nullptr, nullptr, qkv, NTOK, QKVW, 256);
        cls_attn_kernel<<<NHEAD, 256>>>(qkv, atH, atL);
        {
            dim3 gs((HALFN + 63) / 64, (NKEY + 63) / 64, NGRP);
            space_scores_kernel<<<gs, 256>>>(qkv, S);
            softmax_kernel<<<NGRP * HALFN, 128>>>(S);
            dim3 ga((HALFN + 63) / 64, 1, NGRP);
            space_av_kernel<<<ga, 256>>>(S, qkv, atH, atL);
        }
        gemm(atH, atL, wosH + (size_t)i * 256 * D, wosL + (size_t)i * 256 * D,
             s_out_b + i * D, x, x, NTOK, D, 256);

        // ---------------- GEGLU FF ----------------
        layernorm_pack_kernel<<<NTOK, 256>>>(x, f_ln_g + i * D, f_ln_b + i * D, xnH, xnL);
        gemm(xnH, xnL, w1H + (size_t)i * 256 * FF1, w1L + (size_t)i * 256 * FF1,
             f_b1 + i * FF1, nullptr, hbuf, NTOK, FF1, 256);
        geglu_kernel<<<(NTOK * 1024 + 255) / 256, 256>>>(hbuf, acH, acL);
        gemm(acH, acL, w2H + (size_t)i * 1024 * D, w2L + (size_t)i * 1024 * D,
             f_b2 + i * D, x, x, NTOK, D, 1024);
    }

    // ---- final LN on cls + head ----
    layernorm_kernel<<<1, 256>>>(x, o_ln_g, o_ln_b, xn);
    head_kernel<<<1, 64>>>(xn, o_w, o_b, out);
}